// round 1
// baseline (speedup 1.0000x reference)
#include <cuda_runtime.h>
#include <math.h>

#define N_TOK 4096
#define DIM 320
#define HEADS 8
#define DHEAD 40
#define CTX_DIM 768
#define M_CTX 77
#define FF_INNER 1280
#define SIM_STRIDE 80
#define SCALE 0.15811388300841898f

// ---------------- scratch (device globals; no allocation allowed) ------------
__device__ float g_h[N_TOK * DIM];
__device__ float g_q[N_TOK * DIM];
__device__ float g_k[N_TOK * DIM];
__device__ float g_v[N_TOK * DIM];
__device__ float g_o[N_TOK * DIM];
__device__ float g_kc[M_CTX * DIM];
__device__ float g_vc[M_CTX * DIM];
__device__ float g_sim[HEADS * N_TOK * SIM_STRIDE];
__device__ float g_ff[N_TOK * 2 * FF_INNER];
__device__ float g_gg[N_TOK * FF_INNER];

// ---------------- LayerNorm ---------------------------------------------------
__global__ __launch_bounds__(128) void ln_kernel(const float* __restrict__ x,
                                                 const float* __restrict__ g,
                                                 const float* __restrict__ b,
                                                 float* __restrict__ out) {
    int row = blockIdx.x;
    const float* xr = x + row * DIM;
    float s = 0.f, s2 = 0.f;
    for (int i = threadIdx.x; i < DIM; i += 128) {
        float v = xr[i];
        s += v; s2 += v * v;
    }
    #pragma unroll
    for (int off = 16; off; off >>= 1) {
        s  += __shfl_xor_sync(~0u, s, off);
        s2 += __shfl_xor_sync(~0u, s2, off);
    }
    __shared__ float rs[4], rs2[4];
    int w = threadIdx.x >> 5, lane = threadIdx.x & 31;
    if (lane == 0) { rs[w] = s; rs2[w] = s2; }
    __syncthreads();
    s  = rs[0] + rs[1] + rs[2] + rs[3];
    s2 = rs2[0] + rs2[1] + rs2[2] + rs2[3];
    float mu = s * (1.f / DIM);
    float var = s2 * (1.f / DIM) - mu * mu;
    float rstd = rsqrtf(var + 1e-5f);
    float* orow = out + row * DIM;
    for (int i = threadIdx.x; i < DIM; i += 128)
        orow[i] = (xr[i] - mu) * rstd * g[i] + b[i];
}

// ---------------- SGEMM 64x64x16, 4x4 micro-tile ------------------------------
template <bool BIAS, bool RES>
__global__ __launch_bounds__(256) void sgemm_kernel(
    const float* __restrict__ A, const float* __restrict__ B,
    const float* __restrict__ bias, const float* __restrict__ res,
    float* __restrict__ C, int M, int N, int K)
{
    __shared__ float As[16][64];   // As[k][m]
    __shared__ float Bs[16][64];   // Bs[k][n]
    int tx = threadIdx.x & 15;
    int ty = threadIdx.x >> 4;
    int bm = blockIdx.y * 64, bn = blockIdx.x * 64;
    float acc[4][4];
    #pragma unroll
    for (int r = 0; r < 4; r++)
        #pragma unroll
        for (int c = 0; c < 4; c++) acc[r][c] = 0.f;

    for (int k0 = 0; k0 < K; k0 += 16) {
        #pragma unroll
        for (int i = threadIdx.x; i < 64 * 16; i += 256) {
            int m = i >> 4, kk = i & 15;
            int gm = bm + m;
            As[kk][m] = (gm < M) ? A[(size_t)gm * K + k0 + kk] : 0.f;
        }
        #pragma unroll
        for (int i = threadIdx.x; i < 16 * 64; i += 256) {
            int kk = i >> 6, n = i & 63;
            int gn = bn + n;
            Bs[kk][n] = (gn < N) ? B[(size_t)(k0 + kk) * N + gn] : 0.f;
        }
        __syncthreads();
        #pragma unroll
        for (int kk = 0; kk < 16; kk++) {
            float a[4], bb[4];
            #pragma unroll
            for (int r = 0; r < 4; r++) a[r] = As[kk][ty * 4 + r];
            #pragma unroll
            for (int c = 0; c < 4; c++) bb[c] = Bs[kk][tx * 4 + c];
            #pragma unroll
            for (int r = 0; r < 4; r++)
                #pragma unroll
                for (int c = 0; c < 4; c++) acc[r][c] += a[r] * bb[c];
        }
        __syncthreads();
    }
    #pragma unroll
    for (int r = 0; r < 4; r++) {
        int gm = bm + ty * 4 + r;
        if (gm >= M) continue;
        #pragma unroll
        for (int c = 0; c < 4; c++) {
            int gn = bn + tx * 4 + c;
            if (gn >= N) continue;
            float vv = acc[r][c];
            if (BIAS) vv += bias[gn];
            if (RES) vv += res[(size_t)gm * N + gn];
            C[(size_t)gm * N + gn] = vv;
        }
    }
}

// ---------------- self-attention (flash-style) --------------------------------
__global__ __launch_bounds__(128) void self_attn_kernel(
    const float* __restrict__ q, const float* __restrict__ k,
    const float* __restrict__ v, float* __restrict__ out)
{
    __shared__ float4 Ks[64 * 10];
    __shared__ float4 Vs[64 * 10];
    int head = blockIdx.y;
    int qi = blockIdx.x * 128 + threadIdx.x;

    float4 q4[10];
    const float4* qp = (const float4*)(q + (size_t)qi * DIM + head * DHEAD);
    #pragma unroll
    for (int i = 0; i < 10; i++) {
        float4 t = qp[i];
        t.x *= SCALE; t.y *= SCALE; t.z *= SCALE; t.w *= SCALE;
        q4[i] = t;
    }
    float m = -1e30f, l = 0.f;
    float4 acc[10];
    #pragma unroll
    for (int i = 0; i < 10; i++) acc[i] = make_float4(0.f, 0.f, 0.f, 0.f);

    for (int kt = 0; kt < N_TOK; kt += 64) {
        __syncthreads();
        #pragma unroll
        for (int idx = threadIdx.x; idx < 640; idx += 128) {
            int row = idx / 10, c = idx % 10;
            size_t goff = (size_t)(kt + row) * DIM + head * DHEAD + c * 4;
            Ks[idx] = *(const float4*)(k + goff);
            Vs[idx] = *(const float4*)(v + goff);
        }
        __syncthreads();
        for (int j = 0; j < 64; j++) {
            float s0 = 0.f, s1 = 0.f, s2 = 0.f, s3 = 0.f;
            #pragma unroll
            for (int i = 0; i < 10; i++) {
                float4 kv = Ks[j * 10 + i];
                s0 += q4[i].x * kv.x; s1 += q4[i].y * kv.y;
                s2 += q4[i].z * kv.z; s3 += q4[i].w * kv.w;
            }
            float s = (s0 + s1) + (s2 + s3);
            if (s > m) {
                float corr = __expf(m - s);
                m = s; l *= corr;
                #pragma unroll
                for (int i = 0; i < 10; i++) {
                    acc[i].x *= corr; acc[i].y *= corr;
                    acc[i].z *= corr; acc[i].w *= corr;
                }
            }
            float p = __expf(s - m);
            l += p;
            #pragma unroll
            for (int i = 0; i < 10; i++) {
                float4 vv = Vs[j * 10 + i];
                acc[i].x += p * vv.x; acc[i].y += p * vv.y;
                acc[i].z += p * vv.z; acc[i].w += p * vv.w;
            }
        }
    }
    float inv = 1.f / l;
    float4* op = (float4*)(out + (size_t)qi * DIM + head * DHEAD);
    #pragma unroll
    for (int i = 0; i < 10; i++) {
        float4 t = acc[i];
        t.x *= inv; t.y *= inv; t.z *= inv; t.w *= inv;
        op[i] = t;
    }
}

// ---------------- cross-attention scores --------------------------------------
__global__ __launch_bounds__(128) void cross_scores_kernel(
    const float* __restrict__ q, const float* __restrict__ kc,
    float* __restrict__ sim)
{
    __shared__ float4 Ks[M_CTX * 10];
    int head = blockIdx.y;
    int qi = blockIdx.x * 128 + threadIdx.x;
    for (int idx = threadIdx.x; idx < M_CTX * 10; idx += 128) {
        int row = idx / 10, c = idx % 10;
        Ks[idx] = *(const float4*)(kc + (size_t)row * DIM + head * DHEAD + c * 4);
    }
    __syncthreads();
    float4 q4[10];
    const float4* qp = (const float4*)(q + (size_t)qi * DIM + head * DHEAD);
    #pragma unroll
    for (int i = 0; i < 10; i++) {
        float4 t = qp[i];
        t.x *= SCALE; t.y *= SCALE; t.z *= SCALE; t.w *= SCALE;
        q4[i] = t;
    }
    float* srow = sim + ((size_t)head * N_TOK + qi) * SIM_STRIDE;
    for (int j = 0; j < M_CTX; j++) {
        float s0 = 0.f, s1 = 0.f, s2 = 0.f, s3 = 0.f;
        #pragma unroll
        for (int i = 0; i < 10; i++) {
            float4 kv = Ks[j * 10 + i];
            s0 += q4[i].x * kv.x; s1 += q4[i].y * kv.y;
            s2 += q4[i].z * kv.z; s3 += q4[i].w * kv.w;
        }
        srow[j] = (s0 + s1) + (s2 + s3);
    }
}

// ---------------- FCA mask + softmax (warp per row) ----------------------------
__global__ __launch_bounds__(128) void fca_softmax_kernel(
    float* __restrict__ sim, const float* __restrict__ fam,
    const int* __restrict__ use_fca_p)
{
    __shared__ float fam_s[M_CTX * M_CTX];
    __shared__ float srow[4][M_CTX];
    int use_fca = *use_fca_p;
    for (int i = threadIdx.x; i < M_CTX * M_CTX; i += 128)
        fam_s[i] = fam[i];
    int w = threadIdx.x >> 5, lane = threadIdx.x & 31;
    int head = blockIdx.y;
    int qi = blockIdx.x * 4 + w;
    float* grow = sim + ((size_t)head * N_TOK + qi) * SIM_STRIDE;
    for (int d = lane; d < M_CTX; d += 32) srow[w][d] = grow[d];
    __syncthreads();

    int dd[3] = { lane, lane + 32, lane + 64 };
    if (use_fca != 0) {
        float f[3];
        float fmax_local = 0.f;
        #pragma unroll
        for (int t = 0; t < 3; t++) {
            f[t] = -1.f;
            int d = dd[t];
            if (d < M_CTX) {
                float a = 0.f;
                for (int kk = 0; kk < M_CTX; kk++)
                    a += srow[w][kk] * fam_s[d * M_CTX + kk];
                f[t] = fminf(fabsf(a), 1.f);
                fmax_local = fmaxf(fmax_local, f[t]);
            }
        }
        #pragma unroll
        for (int off = 16; off; off >>= 1)
            fmax_local = fmaxf(fmax_local, __shfl_xor_sync(~0u, fmax_local, off));
        float denom = fmax_local + 1e-6f;
        __syncwarp();
        #pragma unroll
        for (int t = 0; t < 3; t++) {
            int d = dd[t];
            if (d < M_CTX) {
                float keep = (f[t] / denom > 0.6f) ? 0.f : -50.f;
                srow[w][d] += keep;
            }
        }
        __syncwarp();
    }
    // softmax over 77 keys
    float mloc = -1e30f;
    #pragma unroll
    for (int t = 0; t < 3; t++)
        if (dd[t] < M_CTX) mloc = fmaxf(mloc, srow[w][dd[t]]);
    #pragma unroll
    for (int off = 16; off; off >>= 1)
        mloc = fmaxf(mloc, __shfl_xor_sync(~0u, mloc, off));
    float pv[3]; float ssum = 0.f;
    #pragma unroll
    for (int t = 0; t < 3; t++) {
        pv[t] = 0.f;
        if (dd[t] < M_CTX) { pv[t] = __expf(srow[w][dd[t]] - mloc); ssum += pv[t]; }
    }
    #pragma unroll
    for (int off = 16; off; off >>= 1)
        ssum += __shfl_xor_sync(~0u, ssum, off);
    float inv = 1.f / ssum;
    #pragma unroll
    for (int t = 0; t < 3; t++)
        if (dd[t] < M_CTX) grow[dd[t]] = pv[t] * inv;
}

// ---------------- cross-attention AV -------------------------------------------
__global__ __launch_bounds__(128) void cross_av_kernel(
    const float* __restrict__ sim, const float* __restrict__ vc,
    float* __restrict__ out)
{
    __shared__ float4 Vs[M_CTX * 10];
    int head = blockIdx.y;
    int qi = blockIdx.x * 128 + threadIdx.x;
    for (int idx = threadIdx.x; idx < M_CTX * 10; idx += 128) {
        int row = idx / 10, c = idx % 10;
        Vs[idx] = *(const float4*)(vc + (size_t)row * DIM + head * DHEAD + c * 4);
    }
    __syncthreads();
    const float* srow = sim + ((size_t)head * N_TOK + qi) * SIM_STRIDE;
    float4 acc[10];
    #pragma unroll
    for (int i = 0; i < 10; i++) acc[i] = make_float4(0.f, 0.f, 0.f, 0.f);
    for (int j = 0; j < M_CTX; j++) {
        float p = srow[j];
        #pragma unroll
        for (int i = 0; i < 10; i++) {
            float4 vv = Vs[j * 10 + i];
            acc[i].x += p * vv.x; acc[i].y += p * vv.y;
            acc[i].z += p * vv.z; acc[i].w += p * vv.w;
        }
    }
    float4* op = (float4*)(out + (size_t)qi * DIM + head * DHEAD);
    #pragma unroll
    for (int i = 0; i < 10; i++) op[i] = acc[i];
}

// ---------------- GEGLU ---------------------------------------------------------
__global__ __launch_bounds__(256) void geglu_kernel(const float* __restrict__ ff,
                                                    float* __restrict__ out) {
    int idx = blockIdx.x * 256 + threadIdx.x;
    if (idx >= N_TOK * FF_INNER) return;
    int row = idx / FF_INNER, col = idx - row * FF_INNER;
    float a = ff[(size_t)row * 2 * FF_INNER + col];
    float gt = ff[(size_t)row * 2 * FF_INNER + FF_INNER + col];
    float ge = 0.5f * gt * (1.f + erff(gt * 0.70710678118654752f));
    out[idx] = a * ge;
}

// ---------------- launch ---------------------------------------------------------
extern "C" void kernel_launch(void* const* d_in, const int* in_sizes, int n_in,
                              void* d_out, int out_size)
{
    const float* x    = (const float*)d_in[0];
    const float* ctx  = (const float*)d_in[1];
    const float* fam  = (const float*)d_in[2];
    const float* g1   = (const float*)d_in[3];
    const float* b1   = (const float*)d_in[4];
    const float* g2   = (const float*)d_in[5];
    const float* b2   = (const float*)d_in[6];
    const float* g3   = (const float*)d_in[7];
    const float* b3   = (const float*)d_in[8];
    const float* Wq1  = (const float*)d_in[9];
    const float* Wk1  = (const float*)d_in[10];
    const float* Wv1  = (const float*)d_in[11];
    const float* Wo1  = (const float*)d_in[12];
    const float* bo1  = (const float*)d_in[13];
    const float* Wq2  = (const float*)d_in[14];
    const float* Wk2  = (const float*)d_in[15];
    const float* Wv2  = (const float*)d_in[16];
    const float* Wo2  = (const float*)d_in[17];
    const float* bo2  = (const float*)d_in[18];
    const float* Wff1 = (const float*)d_in[19];
    const float* bff1 = (const float*)d_in[20];
    const float* Wff2 = (const float*)d_in[21];
    const float* bff2 = (const float*)d_in[22];
    const int*   ufca = (const int*)d_in[23];
    float* out = (float*)d_out;

    float *h, *q, *k, *v, *o, *kc, *vc, *sim, *ff, *gg;
    cudaGetSymbolAddress((void**)&h,  g_h);
    cudaGetSymbolAddress((void**)&q,  g_q);
    cudaGetSymbolAddress((void**)&k,  g_k);
    cudaGetSymbolAddress((void**)&v,  g_v);
    cudaGetSymbolAddress((void**)&o,  g_o);
    cudaGetSymbolAddress((void**)&kc, g_kc);
    cudaGetSymbolAddress((void**)&vc, g_vc);
    cudaGetSymbolAddress((void**)&sim, g_sim);
    cudaGetSymbolAddress((void**)&ff, g_ff);
    cudaGetSymbolAddress((void**)&gg, g_gg);

    dim3 gemm_mm(DIM / 64, N_TOK / 64);        // (5,64) for 4096x320
    dim3 gemm_ctx(DIM / 64, 2);                // 77 rows -> 2 tiles
    dim3 gemm_ff1(2 * FF_INNER / 64, N_TOK / 64);

    // --- block 1: self-attention ---
    ln_kernel<<<N_TOK, 128>>>(x, g1, b1, h);
    sgemm_kernel<false, false><<<gemm_mm, 256>>>(h, Wq1, nullptr, nullptr, q, N_TOK, DIM, DIM);
    sgemm_kernel<false, false><<<gemm_mm, 256>>>(h, Wk1, nullptr, nullptr, k, N_TOK, DIM, DIM);
    sgemm_kernel<false, false><<<gemm_mm, 256>>>(h, Wv1, nullptr, nullptr, v, N_TOK, DIM, DIM);
    self_attn_kernel<<<dim3(N_TOK / 128, HEADS), 128>>>(q, k, v, o);
    sgemm_kernel<true, true><<<gemm_mm, 256>>>(o, Wo1, bo1, x, out, N_TOK, DIM, DIM);

    // --- block 2: cross-attention with FCA ---
    ln_kernel<<<N_TOK, 128>>>(out, g2, b2, h);
    sgemm_kernel<false, false><<<gemm_mm, 256>>>(h, Wq2, nullptr, nullptr, q, N_TOK, DIM, DIM);
    sgemm_kernel<false, false><<<gemm_ctx, 256>>>(ctx, Wk2, nullptr, nullptr, kc, M_CTX, DIM, CTX_DIM);
    sgemm_kernel<false, false><<<gemm_ctx, 256>>>(ctx, Wv2, nullptr, nullptr, vc, M_CTX, DIM, CTX_DIM);
    cross_scores_kernel<<<dim3(N_TOK / 128, HEADS), 128>>>(q, kc, sim);
    fca_softmax_kernel<<<dim3(N_TOK / 4, HEADS), 128>>>(sim, fam, ufca);
    cross_av_kernel<<<dim3(N_TOK / 128, HEADS), 128>>>(sim, vc, o);
    sgemm_kernel<true, true><<<gemm_mm, 256>>>(o, Wo2, bo2, out, out, N_TOK, DIM, DIM);

    // --- block 3: GEGLU feed-forward ---
    ln_kernel<<<N_TOK, 128>>>(out, g3, b3, h);
    sgemm_kernel<true, false><<<gemm_ff1, 256>>>(h, Wff1, bff1, nullptr, ff, N_TOK, 2 * FF_INNER, DIM);
    geglu_kernel<<<(N_TOK * FF_INNER + 255) / 256, 256>>>(ff, gg);
    sgemm_kernel<true, true><<<gemm_mm, 256>>>(gg, Wff2, bff2, out, out, N_TOK, DIM, FF_INNER);
}

// round 2
// speedup vs baseline: 1.0163x; 1.0163x over previous
#include <cuda_runtime.h>
#include <math.h>

#define N_TOK 4096
#define DIM 320
#define HEADS 8
#define DHEAD 40
#define CTX_DIM 768
#define M_CTX 77
#define FF_INNER 1280
#define SIM_STRIDE 80
#define SCALE 0.15811388300841898f

typedef unsigned long long ull;

// ---------------- f32x2 packed-math helpers (Blackwell FFMA2) ----------------
__device__ __forceinline__ ull dup2(float x) {
    ull r; asm("mov.b64 %0, {%1, %1};" : "=l"(r) : "f"(x)); return r;
}
__device__ __forceinline__ void fma2(ull& d, ull a, ull b) {
    asm("fma.rn.f32x2 %0, %1, %2, %0;" : "+l"(d) : "l"(a), "l"(b));
}
__device__ __forceinline__ ull mul2(ull a, ull b) {
    ull r; asm("mul.rn.f32x2 %0, %1, %2;" : "=l"(r) : "l"(a), "l"(b)); return r;
}
__device__ __forceinline__ ull add2(ull a, ull b) {
    ull r; asm("add.rn.f32x2 %0, %1, %2;" : "=l"(r) : "l"(a), "l"(b)); return r;
}
__device__ __forceinline__ float2 unpack2(ull v) {
    float2 r; asm("mov.b64 {%0, %1}, %2;" : "=f"(r.x), "=f"(r.y) : "l"(v)); return r;
}
__device__ __forceinline__ float hadd2(ull v) {
    float2 r = unpack2(v); return r.x + r.y;
}

// ---------------- scratch (device globals; no allocation allowed) ------------
__device__ float g_h[N_TOK * DIM];
__device__ float g_q[N_TOK * DIM];
__device__ float g_k[N_TOK * DIM];
__device__ float g_v[N_TOK * DIM];
__device__ float g_o[N_TOK * DIM];
__device__ float g_kc[M_CTX * DIM];
__device__ float g_vc[M_CTX * DIM];
__device__ float g_sim[HEADS * N_TOK * SIM_STRIDE];
__device__ float g_ff[N_TOK * 2 * FF_INNER];
__device__ float g_gg[N_TOK * FF_INNER];

// ---------------- LayerNorm ---------------------------------------------------
__global__ __launch_bounds__(128) void ln_kernel(const float* __restrict__ x,
                                                 const float* __restrict__ g,
                                                 const float* __restrict__ b,
                                                 float* __restrict__ out) {
    int row = blockIdx.x;
    const float* xr = x + row * DIM;
    float s = 0.f, s2 = 0.f;
    for (int i = threadIdx.x; i < DIM; i += 128) {
        float v = xr[i];
        s += v; s2 += v * v;
    }
    #pragma unroll
    for (int off = 16; off; off >>= 1) {
        s  += __shfl_xor_sync(~0u, s, off);
        s2 += __shfl_xor_sync(~0u, s2, off);
    }
    __shared__ float rs[4], rs2[4];
    int w = threadIdx.x >> 5, lane = threadIdx.x & 31;
    if (lane == 0) { rs[w] = s; rs2[w] = s2; }
    __syncthreads();
    s  = rs[0] + rs[1] + rs[2] + rs[3];
    s2 = rs2[0] + rs2[1] + rs2[2] + rs2[3];
    float mu = s * (1.f / DIM);
    float var = s2 * (1.f / DIM) - mu * mu;
    float rstd = rsqrtf(var + 1e-5f);
    float* orow = out + row * DIM;
    for (int i = threadIdx.x; i < DIM; i += 128)
        orow[i] = (xr[i] - mu) * rstd * g[i] + b[i];
}

// ---------------- SGEMM 128x64x16, 8x4 micro-tile, f32x2 FMAs ------------------
// z-batched: blockIdx.z selects (B, C) pair for fused multi-weight GEMMs.
template <bool BIAS, bool RES>
__global__ __launch_bounds__(256) void sgemm_kernel(
    const float* __restrict__ A,
    const float* __restrict__ B0, const float* __restrict__ B1, const float* __restrict__ B2,
    const float* __restrict__ bias, const float* __restrict__ res,
    float* __restrict__ C0, float* __restrict__ C1, float* __restrict__ C2,
    int M, int N, int K)
{
    const float* B = (blockIdx.z == 0) ? B0 : (blockIdx.z == 1 ? B1 : B2);
    float* C       = (blockIdx.z == 0) ? C0 : (blockIdx.z == 1 ? C1 : C2);

    __shared__ float As[16][132];   // [k][m], +4 pad => <=2-way STS conflicts, 16B-aligned rows
    __shared__ float Bs[16][64];    // [k][n]

    int t = threadIdx.x;
    int tx = t & 15, ty = t >> 4;
    int bm = blockIdx.y * 128, bn = blockIdx.x * 64;
    int m0 = ty * 8, n0 = tx * 4;

    ull acc[4][4];
    #pragma unroll
    for (int p = 0; p < 4; p++)
        #pragma unroll
        for (int n = 0; n < 4; n++) acc[p][n] = 0ull;

    for (int k0 = 0; k0 < K; k0 += 16) {
        // A: 512 float4 loads, transposed store into As[k][m]
        #pragma unroll
        for (int i = 0; i < 2; i++) {
            int idx = t + i * 256;
            int row = idx >> 2;
            int kg  = (idx & 3) * 4;
            int gm = bm + row;
            float4 av = make_float4(0.f, 0.f, 0.f, 0.f);
            if (gm < M) av = *(const float4*)(A + (size_t)gm * K + k0 + kg);
            As[kg + 0][row] = av.x;
            As[kg + 1][row] = av.y;
            As[kg + 2][row] = av.z;
            As[kg + 3][row] = av.w;
        }
        // B: 256 float4 loads, direct
        {
            int kk = t >> 4, nc = (t & 15) * 4;
            *(float4*)&Bs[kk][nc] = *(const float4*)(B + (size_t)(k0 + kk) * N + bn + nc);
        }
        __syncthreads();
        #pragma unroll
        for (int kk = 0; kk < 16; kk++) {
            ulonglong2 a01 = *(const ulonglong2*)&As[kk][m0];
            ulonglong2 a23 = *(const ulonglong2*)&As[kk][m0 + 4];
            float4 bv = *(const float4*)&Bs[kk][n0];
            ull bd0 = dup2(bv.x), bd1 = dup2(bv.y), bd2 = dup2(bv.z), bd3 = dup2(bv.w);
            fma2(acc[0][0], a01.x, bd0); fma2(acc[0][1], a01.x, bd1);
            fma2(acc[0][2], a01.x, bd2); fma2(acc[0][3], a01.x, bd3);
            fma2(acc[1][0], a01.y, bd0); fma2(acc[1][1], a01.y, bd1);
            fma2(acc[1][2], a01.y, bd2); fma2(acc[1][3], a01.y, bd3);
            fma2(acc[2][0], a23.x, bd0); fma2(acc[2][1], a23.x, bd1);
            fma2(acc[2][2], a23.x, bd2); fma2(acc[2][3], a23.x, bd3);
            fma2(acc[3][0], a23.y, bd0); fma2(acc[3][1], a23.y, bd1);
            fma2(acc[3][2], a23.y, bd2); fma2(acc[3][3], a23.y, bd3);
        }
        __syncthreads();
    }

    int gn = bn + n0;
    float4 bsv = make_float4(0.f, 0.f, 0.f, 0.f);
    if (BIAS) bsv = *(const float4*)&bias[gn];
    #pragma unroll
    for (int p = 0; p < 4; p++) {
        float2 c0 = unpack2(acc[p][0]), c1 = unpack2(acc[p][1]);
        float2 c2 = unpack2(acc[p][2]), c3 = unpack2(acc[p][3]);
        float4 rlo = make_float4(c0.x + bsv.x, c1.x + bsv.y, c2.x + bsv.z, c3.x + bsv.w);
        float4 rhi = make_float4(c0.y + bsv.x, c1.y + bsv.y, c2.y + bsv.z, c3.y + bsv.w);
        int gm_lo = bm + m0 + 2 * p;
        if (gm_lo < M) {
            if (RES) {
                float4 rv = *(const float4*)(res + (size_t)gm_lo * N + gn);
                rlo.x += rv.x; rlo.y += rv.y; rlo.z += rv.z; rlo.w += rv.w;
            }
            *(float4*)(C + (size_t)gm_lo * N + gn) = rlo;
        }
        if (gm_lo + 1 < M) {
            if (RES) {
                float4 rv = *(const float4*)(res + (size_t)(gm_lo + 1) * N + gn);
                rhi.x += rv.x; rhi.y += rv.y; rhi.z += rv.z; rhi.w += rv.w;
            }
            *(float4*)(C + (size_t)(gm_lo + 1) * N + gn) = rhi;
        }
    }
}

// ---------------- self-attention (flash-style, f32x2) --------------------------
__global__ __launch_bounds__(64) void self_attn_kernel(
    const float* __restrict__ q, const float* __restrict__ k,
    const float* __restrict__ v, float* __restrict__ out)
{
    __shared__ ulonglong2 Ks[64 * 10];
    __shared__ ulonglong2 Vs[64 * 10];
    int head = blockIdx.y;
    int qi = blockIdx.x * 64 + threadIdx.x;

    ull q2[20];
    {
        const ulonglong2* qp = (const ulonglong2*)(q + (size_t)qi * DIM + head * DHEAD);
        ull sc = dup2(SCALE);
        #pragma unroll
        for (int i = 0; i < 10; i++) {
            ulonglong2 t = qp[i];
            q2[2 * i]     = mul2(t.x, sc);
            q2[2 * i + 1] = mul2(t.y, sc);
        }
    }
    float m = -1e30f, l = 0.f;
    ull acc[20];
    #pragma unroll
    for (int i = 0; i < 20; i++) acc[i] = 0ull;

    for (int kt = 0; kt < N_TOK; kt += 64) {
        __syncthreads();
        #pragma unroll
        for (int idx = threadIdx.x; idx < 640; idx += 64) {
            int row = idx / 10, c = idx % 10;
            size_t goff = (size_t)(kt + row) * DIM + head * DHEAD + c * 4;
            Ks[idx] = *(const ulonglong2*)(k + goff);
            Vs[idx] = *(const ulonglong2*)(v + goff);
        }
        __syncthreads();
        for (int j = 0; j < 64; j++) {
            ull sa = 0ull, sb = 0ull, sc_ = 0ull, sd = 0ull;
            #pragma unroll
            for (int i = 0; i < 10; i += 2) {
                ulonglong2 k0 = Ks[j * 10 + i];
                ulonglong2 k1 = Ks[j * 10 + i + 1];
                fma2(sa, q2[2 * i],     k0.x);
                fma2(sb, q2[2 * i + 1], k0.y);
                fma2(sc_, q2[2 * i + 2], k1.x);
                fma2(sd, q2[2 * i + 3], k1.y);
            }
            float s = hadd2(add2(add2(sa, sb), add2(sc_, sd)));
            if (s > m) {
                float corr = __expf(m - s);
                m = s; l *= corr;
                ull cd = dup2(corr);
                #pragma unroll
                for (int i = 0; i < 20; i++) acc[i] = mul2(acc[i], cd);
            }
            float p = __expf(s - m);
            l += p;
            ull pd = dup2(p);
            #pragma unroll
            for (int i = 0; i < 10; i++) {
                ulonglong2 vv = Vs[j * 10 + i];
                fma2(acc[2 * i],     pd, vv.x);
                fma2(acc[2 * i + 1], pd, vv.y);
            }
        }
    }
    ull invd = dup2(1.f / l);
    ulonglong2* op = (ulonglong2*)(out + (size_t)qi * DIM + head * DHEAD);
    #pragma unroll
    for (int i = 0; i < 10; i++) {
        ulonglong2 t;
        t.x = mul2(acc[2 * i], invd);
        t.y = mul2(acc[2 * i + 1], invd);
        op[i] = t;
    }
}

// ---------------- cross-attention scores (f32x2) --------------------------------
__global__ __launch_bounds__(128) void cross_scores_kernel(
    const float* __restrict__ q, const float* __restrict__ kc,
    float* __restrict__ sim)
{
    __shared__ ulonglong2 Ks[M_CTX * 10];
    int head = blockIdx.y;
    int qi = blockIdx.x * 128 + threadIdx.x;
    for (int idx = threadIdx.x; idx < M_CTX * 10; idx += 128) {
        int row = idx / 10, c = idx % 10;
        Ks[idx] = *(const ulonglong2*)(kc + (size_t)row * DIM + head * DHEAD + c * 4);
    }
    __syncthreads();
    ull q2[20];
    {
        const ulonglong2* qp = (const ulonglong2*)(q + (size_t)qi * DIM + head * DHEAD);
        ull sc = dup2(SCALE);
        #pragma unroll
        for (int i = 0; i < 10; i++) {
            ulonglong2 t = qp[i];
            q2[2 * i]     = mul2(t.x, sc);
            q2[2 * i + 1] = mul2(t.y, sc);
        }
    }
    float* srow = sim + ((size_t)head * N_TOK + qi) * SIM_STRIDE;
    for (int j = 0; j < M_CTX; j++) {
        ull sa = 0ull, sb = 0ull, sc_ = 0ull, sd = 0ull;
        #pragma unroll
        for (int i = 0; i < 10; i += 2) {
            ulonglong2 k0 = Ks[j * 10 + i];
            ulonglong2 k1 = Ks[j * 10 + i + 1];
            fma2(sa, q2[2 * i],     k0.x);
            fma2(sb, q2[2 * i + 1], k0.y);
            fma2(sc_, q2[2 * i + 2], k1.x);
            fma2(sd, q2[2 * i + 3], k1.y);
        }
        srow[j] = hadd2(add2(add2(sa, sb), add2(sc_, sd)));
    }
}

// ---------------- FCA mask + softmax (warp per row) ----------------------------
__global__ __launch_bounds__(128) void fca_softmax_kernel(
    float* __restrict__ sim, const float* __restrict__ fam,
    const int* __restrict__ use_fca_p)
{
    __shared__ float fam_s[M_CTX * M_CTX];
    __shared__ float srow[4][M_CTX];
    int use_fca = *use_fca_p;
    for (int i = threadIdx.x; i < M_CTX * M_CTX; i += 128)
        fam_s[i] = fam[i];
    int w = threadIdx.x >> 5, lane = threadIdx.x & 31;
    int head = blockIdx.y;
    int qi = blockIdx.x * 4 + w;
    float* grow = sim + ((size_t)head * N_TOK + qi) * SIM_STRIDE;
    for (int d = lane; d < M_CTX; d += 32) srow[w][d] = grow[d];
    __syncthreads();

    int dd[3] = { lane, lane + 32, lane + 64 };
    if (use_fca != 0) {
        float f[3];
        float fmax_local = 0.f;
        #pragma unroll
        for (int t = 0; t < 3; t++) {
            f[t] = -1.f;
            int d = dd[t];
            if (d < M_CTX) {
                float a = 0.f;
                for (int kk = 0; kk < M_CTX; kk++)
                    a += srow[w][kk] * fam_s[d * M_CTX + kk];
                f[t] = fminf(fabsf(a), 1.f);
                fmax_local = fmaxf(fmax_local, f[t]);
            }
        }
        #pragma unroll
        for (int off = 16; off; off >>= 1)
            fmax_local = fmaxf(fmax_local, __shfl_xor_sync(~0u, fmax_local, off));
        float denom = fmax_local + 1e-6f;
        __syncwarp();
        #pragma unroll
        for (int t = 0; t < 3; t++) {
            int d = dd[t];
            if (d < M_CTX) {
                float keep = (f[t] / denom > 0.6f) ? 0.f : -50.f;
                srow[w][d] += keep;
            }
        }
        __syncwarp();
    }
    float mloc = -1e30f;
    #pragma unroll
    for (int t = 0; t < 3; t++)
        if (dd[t] < M_CTX) mloc = fmaxf(mloc, srow[w][dd[t]]);
    #pragma unroll
    for (int off = 16; off; off >>= 1)
        mloc = fmaxf(mloc, __shfl_xor_sync(~0u, mloc, off));
    float pv[3]; float ssum = 0.f;
    #pragma unroll
    for (int t = 0; t < 3; t++) {
        pv[t] = 0.f;
        if (dd[t] < M_CTX) { pv[t] = __expf(srow[w][dd[t]] - mloc); ssum += pv[t]; }
    }
    #pragma unroll
    for (int off = 16; off; off >>= 1)
        ssum += __shfl_xor_sync(~0u, ssum, off);
    float inv = 1.f / ssum;
    #pragma unroll
    for (int t = 0; t < 3; t++)
        if (dd[t] < M_CTX) grow[dd[t]] = pv[t] * inv;
}

// ---------------- cross-attention AV (f32x2) -------------------------------------
__global__ __launch_bounds__(128) void cross_av_kernel(
    const float* __restrict__ sim, const float* __restrict__ vc,
    float* __restrict__ out)
{
    __shared__ ulonglong2 Vs[M_CTX * 10];
    int head = blockIdx.y;
    int qi = blockIdx.x * 128 + threadIdx.x;
    for (int idx = threadIdx.x; idx < M_CTX * 10; idx += 128) {
        int row = idx / 10, c = idx % 10;
        Vs[idx] = *(const ulonglong2*)(vc + (size_t)row * DIM + head * DHEAD + c * 4);
    }
    __syncthreads();
    const float* srow = sim + ((size_t)head * N_TOK + qi) * SIM_STRIDE;
    ull acc[20];
    #pragma unroll
    for (int i = 0; i < 20; i++) acc[i] = 0ull;
    for (int j = 0; j < M_CTX; j++) {
        ull pd = dup2(srow[j]);
        #pragma unroll
        for (int i = 0; i < 10; i++) {
            ulonglong2 vv = Vs[j * 10 + i];
            fma2(acc[2 * i],     pd, vv.x);
            fma2(acc[2 * i + 1], pd, vv.y);
        }
    }
    ulonglong2* op = (ulonglong2*)(out + (size_t)qi * DIM + head * DHEAD);
    #pragma unroll
    for (int i = 0; i < 10; i++) {
        ulonglong2 t;
        t.x = acc[2 * i];
        t.y = acc[2 * i + 1];
        op[i] = t;
    }
}

// ---------------- GEGLU ---------------------------------------------------------
__global__ __launch_bounds__(256) void geglu_kernel(const float* __restrict__ ff,
                                                    float* __restrict__ out) {
    int idx = blockIdx.x * 256 + threadIdx.x;
    if (idx >= N_TOK * FF_INNER) return;
    int row = idx / FF_INNER, col = idx - row * FF_INNER;
    float a = ff[(size_t)row * 2 * FF_INNER + col];
    float gt = ff[(size_t)row * 2 * FF_INNER + FF_INNER + col];
    float ge = 0.5f * gt * (1.f + erff(gt * 0.70710678118654752f));
    out[idx] = a * ge;
}

// ---------------- launch ---------------------------------------------------------
extern "C" void kernel_launch(void* const* d_in, const int* in_sizes, int n_in,
                              void* d_out, int out_size)
{
    const float* x    = (const float*)d_in[0];
    const float* ctx  = (const float*)d_in[1];
    const float* fam  = (const float*)d_in[2];
    const float* g1   = (const float*)d_in[3];
    const float* b1   = (const float*)d_in[4];
    const float* g2   = (const float*)d_in[5];
    const float* b2   = (const float*)d_in[6];
    const float* g3   = (const float*)d_in[7];
    const float* b3   = (const float*)d_in[8];
    const float* Wq1  = (const float*)d_in[9];
    const float* Wk1  = (const float*)d_in[10];
    const float* Wv1  = (const float*)d_in[11];
    const float* Wo1  = (const float*)d_in[12];
    const float* bo1  = (const float*)d_in[13];
    const float* Wq2  = (const float*)d_in[14];
    const float* Wk2  = (const float*)d_in[15];
    const float* Wv2  = (const float*)d_in[16];
    const float* Wo2  = (const float*)d_in[17];
    const float* bo2  = (const float*)d_in[18];
    const float* Wff1 = (const float*)d_in[19];
    const float* bff1 = (const float*)d_in[20];
    const float* Wff2 = (const float*)d_in[21];
    const float* bff2 = (const float*)d_in[22];
    const int*   ufca = (const int*)d_in[23];
    float* out = (float*)d_out;

    float *h, *q, *k, *v, *o, *kc, *vc, *sim, *ff, *gg;
    cudaGetSymbolAddress((void**)&h,  g_h);
    cudaGetSymbolAddress((void**)&q,  g_q);
    cudaGetSymbolAddress((void**)&k,  g_k);
    cudaGetSymbolAddress((void**)&v,  g_v);
    cudaGetSymbolAddress((void**)&o,  g_o);
    cudaGetSymbolAddress((void**)&kc, g_kc);
    cudaGetSymbolAddress((void**)&vc, g_vc);
    cudaGetSymbolAddress((void**)&sim, g_sim);
    cudaGetSymbolAddress((void**)&ff, g_ff);
    cudaGetSymbolAddress((void**)&gg, g_gg);

    dim3 g_mm(DIM / 64, N_TOK / 128, 1);          // (5, 32)
    dim3 g_qkv(DIM / 64, N_TOK / 128, 3);         // fused Q/K/V
    dim3 g_ctx2(DIM / 64, 1, 2);                  // fused ctx K/V (M=77)
    dim3 g_ff1(2 * FF_INNER / 64, N_TOK / 128, 1);

    // --- block 1: self-attention ---
    ln_kernel<<<N_TOK, 128>>>(x, g1, b1, h);
    sgemm_kernel<false, false><<<g_qkv, 256>>>(h, Wq1, Wk1, Wv1, nullptr, nullptr,
                                               q, k, v, N_TOK, DIM, DIM);
    self_attn_kernel<<<dim3(N_TOK / 64, HEADS), 64>>>(q, k, v, o);
    sgemm_kernel<true, true><<<g_mm, 256>>>(o, Wo1, Wo1, Wo1, bo1, x,
                                            out, out, out, N_TOK, DIM, DIM);

    // --- block 2: cross-attention with FCA ---
    ln_kernel<<<N_TOK, 128>>>(out, g2, b2, h);
    sgemm_kernel<false, false><<<g_mm, 256>>>(h, Wq2, Wq2, Wq2, nullptr, nullptr,
                                              q, q, q, N_TOK, DIM, DIM);
    sgemm_kernel<false, false><<<g_ctx2, 256>>>(ctx, Wk2, Wv2, Wv2, nullptr, nullptr,
                                                kc, vc, vc, M_CTX, DIM, CTX_DIM);
    cross_scores_kernel<<<dim3(N_TOK / 128, HEADS), 128>>>(q, kc, sim);
    fca_softmax_kernel<<<dim3(N_TOK / 4, HEADS), 128>>>(sim, fam, ufca);
    cross_av_kernel<<<dim3(N_TOK / 128, HEADS), 128>>>(sim, vc, o);
    sgemm_kernel<true, true><<<g_mm, 256>>>(o, Wo2, Wo2, Wo2, bo2, out,
                                            out, out, out, N_TOK, DIM, DIM);

    // --- block 3: GEGLU feed-forward ---
    ln_kernel<<<N_TOK, 128>>>(out, g3, b3, h);
    sgemm_kernel<true, false><<<g_ff1, 256>>>(h, Wff1, Wff1, Wff1, bff1, nullptr,
                                              ff, ff, ff, N_TOK, 2 * FF_INNER, DIM);
    geglu_kernel<<<(N_TOK * FF_INNER + 255) / 256, 256>>>(ff, gg);
    sgemm_kernel<true, true><<<g_mm, 256>>>(gg, Wff2, Wff2, Wff2, bff2, out,
                                            out, out, out, N_TOK, DIM, FF_INNER);
}

// round 3
// speedup vs baseline: 1.3334x; 1.3121x over previous
#include <cuda_runtime.h>
#include <math.h>

#define N_TOK 4096
#define DIM 320
#define HEADS 8
#define DHEAD 40
#define CTX_DIM 768
#define M_CTX 77
#define FF_INNER 1280
#define SIM_STRIDE 80
#define SCALE 0.15811388300841898f
#define NSPLIT 2
#define KEYS_PER_SPLIT (N_TOK / NSPLIT)
#define QH (HEADS * N_TOK)

typedef unsigned long long ull;

// ---------------- f32x2 packed-math helpers (Blackwell FFMA2) ----------------
__device__ __forceinline__ ull dup2(float x) {
    ull r; asm("mov.b64 %0, {%1, %1};" : "=l"(r) : "f"(x)); return r;
}
__device__ __forceinline__ void fma2(ull& d, ull a, ull b) {
    asm("fma.rn.f32x2 %0, %1, %2, %0;" : "+l"(d) : "l"(a), "l"(b));
}
__device__ __forceinline__ ull mul2(ull a, ull b) {
    ull r; asm("mul.rn.f32x2 %0, %1, %2;" : "=l"(r) : "l"(a), "l"(b)); return r;
}
__device__ __forceinline__ ull add2(ull a, ull b) {
    ull r; asm("add.rn.f32x2 %0, %1, %2;" : "=l"(r) : "l"(a), "l"(b)); return r;
}
__device__ __forceinline__ float2 unpack2(ull v) {
    float2 r; asm("mov.b64 {%0, %1}, %2;" : "=f"(r.x), "=f"(r.y) : "l"(v)); return r;
}
__device__ __forceinline__ float hadd2(ull v) {
    float2 r = unpack2(v); return r.x + r.y;
}

// ---------------- scratch (device globals; no allocation allowed) ------------
__device__ float g_h[N_TOK * DIM];
__device__ float g_q[N_TOK * DIM];
__device__ float g_k[N_TOK * DIM];
__device__ float g_v[N_TOK * DIM];
__device__ float g_o[N_TOK * DIM];
__device__ float g_kc[M_CTX * DIM];
__device__ float g_vc[M_CTX * DIM];
__device__ float g_sim[HEADS * N_TOK * SIM_STRIDE];
__device__ float g_ff[N_TOK * 2 * FF_INNER];
__device__ float g_gg[N_TOK * FF_INNER];
__device__ float g_pacc[NSPLIT * QH * DHEAD];
__device__ float g_pml[NSPLIT * QH * 2];

// ---------------- LayerNorm ---------------------------------------------------
__global__ __launch_bounds__(128) void ln_kernel(const float* __restrict__ x,
                                                 const float* __restrict__ g,
                                                 const float* __restrict__ b,
                                                 float* __restrict__ out) {
    int row = blockIdx.x;
    const float* xr = x + row * DIM;
    float s = 0.f, s2 = 0.f;
    for (int i = threadIdx.x; i < DIM; i += 128) {
        float v = xr[i];
        s += v; s2 += v * v;
    }
    #pragma unroll
    for (int off = 16; off; off >>= 1) {
        s  += __shfl_xor_sync(~0u, s, off);
        s2 += __shfl_xor_sync(~0u, s2, off);
    }
    __shared__ float rs[4], rs2[4];
    int w = threadIdx.x >> 5, lane = threadIdx.x & 31;
    if (lane == 0) { rs[w] = s; rs2[w] = s2; }
    __syncthreads();
    s  = rs[0] + rs[1] + rs[2] + rs[3];
    s2 = rs2[0] + rs2[1] + rs2[2] + rs2[3];
    float mu = s * (1.f / DIM);
    float var = s2 * (1.f / DIM) - mu * mu;
    float rstd = rsqrtf(var + 1e-5f);
    float* orow = out + row * DIM;
    for (int i = threadIdx.x; i < DIM; i += 128)
        orow[i] = (xr[i] - mu) * rstd * g[i] + b[i];
}

// ---------------- SGEMM 128x64x16, double-buffered, f32x2 ----------------------
template <bool BIAS, bool RES>
__global__ __launch_bounds__(256) void sgemm_kernel(
    const float* __restrict__ A,
    const float* B0, const float* B1, const float* B2,
    const float* __restrict__ bias, const float* __restrict__ res,
    float* C0, float* C1, float* C2,
    int M, int N, int K)
{
    const float* __restrict__ B = (blockIdx.z == 0) ? B0 : (blockIdx.z == 1 ? B1 : B2);
    float* __restrict__ C       = (blockIdx.z == 0) ? C0 : (blockIdx.z == 1 ? C1 : C2);

    __shared__ float As[2][16][132];
    __shared__ float Bs[2][16][64];

    int t = threadIdx.x;
    int tx = t & 15, ty = t >> 4;
    int bm = blockIdx.y * 128, bn = blockIdx.x * 64;
    int m0 = ty * 8, n0 = tx * 4;

    int a_row0 = t >> 2;
    int a_row1 = a_row0 + 64;
    int a_kg = (t & 3) * 4;
    int b_kk = t >> 4, b_nc = (t & 15) * 4;
    int gm0 = bm + a_row0, gm1 = bm + a_row1;

    ull acc[4][4];
    #pragma unroll
    for (int p = 0; p < 4; p++)
        #pragma unroll
        for (int n = 0; n < 4; n++) acc[p][n] = 0ull;

    float4 aR0, aR1, bR;
    // prologue: load k-tile 0
    aR0 = (gm0 < M) ? *(const float4*)(A + (size_t)gm0 * K + a_kg) : make_float4(0.f,0.f,0.f,0.f);
    aR1 = (gm1 < M) ? *(const float4*)(A + (size_t)gm1 * K + a_kg) : make_float4(0.f,0.f,0.f,0.f);
    bR  = *(const float4*)(B + (size_t)b_kk * N + bn + b_nc);
    As[0][a_kg + 0][a_row0] = aR0.x; As[0][a_kg + 1][a_row0] = aR0.y;
    As[0][a_kg + 2][a_row0] = aR0.z; As[0][a_kg + 3][a_row0] = aR0.w;
    As[0][a_kg + 0][a_row1] = aR1.x; As[0][a_kg + 1][a_row1] = aR1.y;
    As[0][a_kg + 2][a_row1] = aR1.z; As[0][a_kg + 3][a_row1] = aR1.w;
    *(float4*)&Bs[0][b_kk][b_nc] = bR;
    __syncthreads();

    int nt = K >> 4;
    for (int it = 0; it < nt; it++) {
        int cur = it & 1;
        if (it + 1 < nt) {
            int k0 = (it + 1) << 4;
            aR0 = (gm0 < M) ? *(const float4*)(A + (size_t)gm0 * K + k0 + a_kg) : make_float4(0.f,0.f,0.f,0.f);
            aR1 = (gm1 < M) ? *(const float4*)(A + (size_t)gm1 * K + k0 + a_kg) : make_float4(0.f,0.f,0.f,0.f);
            bR  = *(const float4*)(B + (size_t)(k0 + b_kk) * N + bn + b_nc);
        }
        #pragma unroll
        for (int kk = 0; kk < 16; kk++) {
            ulonglong2 a01 = *(const ulonglong2*)&As[cur][kk][m0];
            ulonglong2 a23 = *(const ulonglong2*)&As[cur][kk][m0 + 4];
            float4 bv = *(const float4*)&Bs[cur][kk][n0];
            ull bd0 = dup2(bv.x), bd1 = dup2(bv.y), bd2 = dup2(bv.z), bd3 = dup2(bv.w);
            fma2(acc[0][0], a01.x, bd0); fma2(acc[0][1], a01.x, bd1);
            fma2(acc[0][2], a01.x, bd2); fma2(acc[0][3], a01.x, bd3);
            fma2(acc[1][0], a01.y, bd0); fma2(acc[1][1], a01.y, bd1);
            fma2(acc[1][2], a01.y, bd2); fma2(acc[1][3], a01.y, bd3);
            fma2(acc[2][0], a23.x, bd0); fma2(acc[2][1], a23.x, bd1);
            fma2(acc[2][2], a23.x, bd2); fma2(acc[2][3], a23.x, bd3);
            fma2(acc[3][0], a23.y, bd0); fma2(acc[3][1], a23.y, bd1);
            fma2(acc[3][2], a23.y, bd2); fma2(acc[3][3], a23.y, bd3);
        }
        if (it + 1 < nt) {
            int nxt = cur ^ 1;
            As[nxt][a_kg + 0][a_row0] = aR0.x; As[nxt][a_kg + 1][a_row0] = aR0.y;
            As[nxt][a_kg + 2][a_row0] = aR0.z; As[nxt][a_kg + 3][a_row0] = aR0.w;
            As[nxt][a_kg + 0][a_row1] = aR1.x; As[nxt][a_kg + 1][a_row1] = aR1.y;
            As[nxt][a_kg + 2][a_row1] = aR1.z; As[nxt][a_kg + 3][a_row1] = aR1.w;
            *(float4*)&Bs[nxt][b_kk][b_nc] = bR;
        }
        __syncthreads();
    }

    int gn = bn + n0;
    float4 bsv = make_float4(0.f, 0.f, 0.f, 0.f);
    if (BIAS) bsv = *(const float4*)&bias[gn];
    #pragma unroll
    for (int p = 0; p < 4; p++) {
        float2 c0 = unpack2(acc[p][0]), c1 = unpack2(acc[p][1]);
        float2 c2 = unpack2(acc[p][2]), c3 = unpack2(acc[p][3]);
        float4 rlo = make_float4(c0.x + bsv.x, c1.x + bsv.y, c2.x + bsv.z, c3.x + bsv.w);
        float4 rhi = make_float4(c0.y + bsv.x, c1.y + bsv.y, c2.y + bsv.z, c3.y + bsv.w);
        int gm_lo = bm + m0 + 2 * p;
        if (gm_lo < M) {
            if (RES) {
                float4 rv = *(const float4*)(res + (size_t)gm_lo * N + gn);
                rlo.x += rv.x; rlo.y += rv.y; rlo.z += rv.z; rlo.w += rv.w;
            }
            *(float4*)(C + (size_t)gm_lo * N + gn) = rlo;
        }
        if (gm_lo + 1 < M) {
            if (RES) {
                float4 rv = *(const float4*)(res + (size_t)(gm_lo + 1) * N + gn);
                rhi.x += rv.x; rhi.y += rv.y; rhi.z += rv.z; rhi.w += rv.w;
            }
            *(float4*)(C + (size_t)(gm_lo + 1) * N + gn) = rhi;
        }
    }
}

// ---------------- self-attention: split-K flash, 4-key ILP ---------------------
__global__ __launch_bounds__(128) void self_attn_kernel(
    const float* __restrict__ q, const float* __restrict__ k,
    const float* __restrict__ v, float* __restrict__ pacc,
    float* __restrict__ pml)
{
    __shared__ ulonglong2 Ks[128 * 10];
    __shared__ ulonglong2 Vs[128 * 10];
    int head = blockIdx.y;
    int split = blockIdx.z;
    int qi = blockIdx.x * 128 + threadIdx.x;
    int kbeg = split * KEYS_PER_SPLIT;

    ull q2[20];
    {
        const ulonglong2* qp = (const ulonglong2*)(q + (size_t)qi * DIM + head * DHEAD);
        ull sc = dup2(SCALE);
        #pragma unroll
        for (int i = 0; i < 10; i++) {
            ulonglong2 tq = qp[i];
            q2[2 * i]     = mul2(tq.x, sc);
            q2[2 * i + 1] = mul2(tq.y, sc);
        }
    }
    float m = -1e30f, l = 0.f;
    ull acc[20];
    #pragma unroll
    for (int i = 0; i < 20; i++) acc[i] = 0ull;

    for (int kt = 0; kt < KEYS_PER_SPLIT; kt += 128) {
        __syncthreads();
        #pragma unroll
        for (int idx = threadIdx.x; idx < 1280; idx += 128) {
            int row = idx / 10, c = idx % 10;
            size_t goff = (size_t)(kbeg + kt + row) * DIM + head * DHEAD + c * 4;
            Ks[idx] = *(const ulonglong2*)(k + goff);
            Vs[idx] = *(const ulonglong2*)(v + goff);
        }
        __syncthreads();
        #pragma unroll 1
        for (int j = 0; j < 128; j += 4) {
            float sf[4];
            #pragma unroll
            for (int kk4 = 0; kk4 < 4; kk4++) {
                ull sa = 0ull, sb = 0ull;
                const ulonglong2* kr = &Ks[(j + kk4) * 10];
                #pragma unroll
                for (int i = 0; i < 10; i++) {
                    ulonglong2 kv = kr[i];
                    fma2(sa, q2[2 * i],     kv.x);
                    fma2(sb, q2[2 * i + 1], kv.y);
                }
                sf[kk4] = hadd2(add2(sa, sb));
            }
            float mn = fmaxf(fmaxf(sf[0], sf[1]), fmaxf(sf[2], sf[3]));
            if (mn > m) {
                float corr = __expf(m - mn);
                l *= corr;
                ull cd = dup2(corr);
                #pragma unroll
                for (int i = 0; i < 20; i++) acc[i] = mul2(acc[i], cd);
                m = mn;
            }
            float e0 = __expf(sf[0] - m), e1 = __expf(sf[1] - m);
            float e2 = __expf(sf[2] - m), e3 = __expf(sf[3] - m);
            l += (e0 + e1) + (e2 + e3);
            ull p0 = dup2(e0), p1 = dup2(e1), p2 = dup2(e2), p3 = dup2(e3);
            const ulonglong2* v0 = &Vs[(j + 0) * 10];
            const ulonglong2* v1 = &Vs[(j + 1) * 10];
            const ulonglong2* v2 = &Vs[(j + 2) * 10];
            const ulonglong2* v3 = &Vs[(j + 3) * 10];
            #pragma unroll
            for (int i = 0; i < 10; i++) {
                ull a0 = acc[2 * i], a1 = acc[2 * i + 1];
                ulonglong2 w0 = v0[i], w1 = v1[i], w2 = v2[i], w3 = v3[i];
                fma2(a0, p0, w0.x); fma2(a1, p0, w0.y);
                fma2(a0, p1, w1.x); fma2(a1, p1, w1.y);
                fma2(a0, p2, w2.x); fma2(a1, p2, w2.y);
                fma2(a0, p3, w3.x); fma2(a1, p3, w3.y);
                acc[2 * i] = a0; acc[2 * i + 1] = a1;
            }
        }
    }
    int p = head * N_TOK + qi;
    ulonglong2* op = (ulonglong2*)(pacc + ((size_t)split * QH + p) * DHEAD);
    #pragma unroll
    for (int i = 0; i < 10; i++) {
        ulonglong2 tv; tv.x = acc[2 * i]; tv.y = acc[2 * i + 1];
        op[i] = tv;
    }
    pml[((size_t)split * QH + p) * 2 + 0] = m;
    pml[((size_t)split * QH + p) * 2 + 1] = l;
}

// ---------------- attention split combine --------------------------------------
__global__ __launch_bounds__(128) void attn_combine_kernel(
    const float* __restrict__ pacc, const float* __restrict__ pml,
    float* __restrict__ out)
{
    int p = blockIdx.x * 128 + threadIdx.x;
    float m0 = pml[p * 2], l0 = pml[p * 2 + 1];
    float m1 = pml[(QH + p) * 2], l1 = pml[(QH + p) * 2 + 1];
    float mm = fmaxf(m0, m1);
    float c0 = __expf(m0 - mm), c1 = __expf(m1 - mm);
    float inv = 1.f / (l0 * c0 + l1 * c1);
    c0 *= inv; c1 *= inv;
    int head = p / N_TOK, qi = p - head * N_TOK;
    const float4* a0 = (const float4*)(pacc + (size_t)p * DHEAD);
    const float4* a1 = (const float4*)(pacc + (size_t)(QH + p) * DHEAD);
    float4* op = (float4*)(out + (size_t)qi * DIM + head * DHEAD);
    #pragma unroll
    for (int i = 0; i < 10; i++) {
        float4 x0 = a0[i], x1 = a1[i];
        op[i] = make_float4(x0.x * c0 + x1.x * c1, x0.y * c0 + x1.y * c1,
                            x0.z * c0 + x1.z * c1, x0.w * c0 + x1.w * c1);
    }
}

// ---------------- cross-attention scores (f32x2) --------------------------------
__global__ __launch_bounds__(128) void cross_scores_kernel(
    const float* __restrict__ q, const float* __restrict__ kc,
    float* __restrict__ sim)
{
    __shared__ ulonglong2 Ks[M_CTX * 10];
    int head = blockIdx.y;
    int qi = blockIdx.x * 128 + threadIdx.x;
    for (int idx = threadIdx.x; idx < M_CTX * 10; idx += 128) {
        int row = idx / 10, c = idx % 10;
        Ks[idx] = *(const ulonglong2*)(kc + (size_t)row * DIM + head * DHEAD + c * 4);
    }
    __syncthreads();
    ull q2[20];
    {
        const ulonglong2* qp = (const ulonglong2*)(q + (size_t)qi * DIM + head * DHEAD);
        ull sc = dup2(SCALE);
        #pragma unroll
        for (int i = 0; i < 10; i++) {
            ulonglong2 tq = qp[i];
            q2[2 * i]     = mul2(tq.x, sc);
            q2[2 * i + 1] = mul2(tq.y, sc);
        }
    }
    float* srow = sim + ((size_t)head * N_TOK + qi) * SIM_STRIDE;
    for (int j = 0; j < M_CTX; j++) {
        ull sa = 0ull, sb = 0ull;
        const ulonglong2* kr = &Ks[j * 10];
        #pragma unroll
        for (int i = 0; i < 10; i++) {
            ulonglong2 kv = kr[i];
            fma2(sa, q2[2 * i],     kv.x);
            fma2(sb, q2[2 * i + 1], kv.y);
        }
        srow[j] = hadd2(add2(sa, sb));
    }
}

// ---------------- FCA mask + softmax (16 rows/block) ----------------------------
__global__ __launch_bounds__(128) void fca_softmax_kernel(
    float* __restrict__ sim, const float* __restrict__ fam,
    const int* __restrict__ use_fca_p)
{
    __shared__ float fam_s[M_CTX * M_CTX];
    __shared__ float srow[16][M_CTX];
    int use_fca = *use_fca_p;
    int head = blockIdx.y;
    int qbase = blockIdx.x * 16;
    for (int i = threadIdx.x; i < M_CTX * M_CTX; i += 128)
        fam_s[i] = fam[i];
    for (int idx = threadIdx.x; idx < 16 * M_CTX; idx += 128) {
        int r = idx / M_CTX, d = idx - r * M_CTX;
        srow[r][d] = sim[((size_t)head * N_TOK + qbase + r) * SIM_STRIDE + d];
    }
    __syncthreads();
    int w = threadIdx.x >> 5, lane = threadIdx.x & 31;
    int dd[3] = { lane, lane + 32, lane + 64 };

    for (int rr = 0; rr < 4; rr++) {
        int r = w * 4 + rr;
        float* grow = sim + ((size_t)head * N_TOK + qbase + r) * SIM_STRIDE;
        if (use_fca != 0) {
            float f[3];
            float fmax_local = 0.f;
            #pragma unroll
            for (int t = 0; t < 3; t++) {
                f[t] = -1.f;
                int d = dd[t];
                if (d < M_CTX) {
                    float a = 0.f;
                    for (int kk = 0; kk < M_CTX; kk++)
                        a += srow[r][kk] * fam_s[d * M_CTX + kk];
                    f[t] = fminf(fabsf(a), 1.f);
                    fmax_local = fmaxf(fmax_local, f[t]);
                }
            }
            #pragma unroll
            for (int off = 16; off; off >>= 1)
                fmax_local = fmaxf(fmax_local, __shfl_xor_sync(~0u, fmax_local, off));
            float denom = fmax_local + 1e-6f;
            __syncwarp();
            #pragma unroll
            for (int t = 0; t < 3; t++) {
                int d = dd[t];
                if (d < M_CTX) {
                    float keep = (f[t] / denom > 0.6f) ? 0.f : -50.f;
                    srow[r][d] += keep;
                }
            }
            __syncwarp();
        }
        float mloc = -1e30f;
        #pragma unroll
        for (int t = 0; t < 3; t++)
            if (dd[t] < M_CTX) mloc = fmaxf(mloc, srow[r][dd[t]]);
        #pragma unroll
        for (int off = 16; off; off >>= 1)
            mloc = fmaxf(mloc, __shfl_xor_sync(~0u, mloc, off));
        float pv[3]; float ssum = 0.f;
        #pragma unroll
        for (int t = 0; t < 3; t++) {
            pv[t] = 0.f;
            if (dd[t] < M_CTX) { pv[t] = __expf(srow[r][dd[t]] - mloc); ssum += pv[t]; }
        }
        #pragma unroll
        for (int off = 16; off; off >>= 1)
            ssum += __shfl_xor_sync(~0u, ssum, off);
        float inv = 1.f / ssum;
        #pragma unroll
        for (int t = 0; t < 3; t++)
            if (dd[t] < M_CTX) grow[dd[t]] = pv[t] * inv;
    }
}

// ---------------- cross-attention AV (f32x2) -------------------------------------
__global__ __launch_bounds__(128) void cross_av_kernel(
    const float* __restrict__ sim, const float* __restrict__ vc,
    float* __restrict__ out)
{
    __shared__ ulonglong2 Vs[M_CTX * 10];
    int head = blockIdx.y;
    int qi = blockIdx.x * 128 + threadIdx.x;
    for (int idx = threadIdx.x; idx < M_CTX * 10; idx += 128) {
        int row = idx / 10, c = idx % 10;
        Vs[idx] = *(const ulonglong2*)(vc + (size_t)row * DIM + head * DHEAD + c * 4);
    }
    __syncthreads();
    const float* srow = sim + ((size_t)head * N_TOK + qi) * SIM_STRIDE;
    ull acc[20];
    #pragma unroll
    for (int i = 0; i < 20; i++) acc[i] = 0ull;
    for (int j = 0; j < M_CTX; j++) {
        ull pd = dup2(srow[j]);
        const ulonglong2* vr = &Vs[j * 10];
        #pragma unroll
        for (int i = 0; i < 10; i++) {
            ulonglong2 vv = vr[i];
            fma2(acc[2 * i],     pd, vv.x);
            fma2(acc[2 * i + 1], pd, vv.y);
        }
    }
    ulonglong2* op = (ulonglong2*)(out + (size_t)qi * DIM + head * DHEAD);
    #pragma unroll
    for (int i = 0; i < 10; i++) {
        ulonglong2 tv;
        tv.x = acc[2 * i];
        tv.y = acc[2 * i + 1];
        op[i] = tv;
    }
}

// ---------------- GEGLU ---------------------------------------------------------
__global__ __launch_bounds__(256) void geglu_kernel(const float* __restrict__ ff,
                                                    float* __restrict__ out) {
    int idx = blockIdx.x * 256 + threadIdx.x;
    if (idx >= N_TOK * FF_INNER) return;
    int row = idx / FF_INNER, col = idx - row * FF_INNER;
    float a = ff[(size_t)row * 2 * FF_INNER + col];
    float gt = ff[(size_t)row * 2 * FF_INNER + FF_INNER + col];
    float ge = 0.5f * gt * (1.f + erff(gt * 0.70710678118654752f));
    out[idx] = a * ge;
}

// ---------------- launch ---------------------------------------------------------
extern "C" void kernel_launch(void* const* d_in, const int* in_sizes, int n_in,
                              void* d_out, int out_size)
{
    const float* x    = (const float*)d_in[0];
    const float* ctx  = (const float*)d_in[1];
    const float* fam  = (const float*)d_in[2];
    const float* g1   = (const float*)d_in[3];
    const float* b1   = (const float*)d_in[4];
    const float* g2   = (const float*)d_in[5];
    const float* b2   = (const float*)d_in[6];
    const float* g3   = (const float*)d_in[7];
    const float* b3   = (const float*)d_in[8];
    const float* Wq1  = (const float*)d_in[9];
    const float* Wk1  = (const float*)d_in[10];
    const float* Wv1  = (const float*)d_in[11];
    const float* Wo1  = (const float*)d_in[12];
    const float* bo1  = (const float*)d_in[13];
    const float* Wq2  = (const float*)d_in[14];
    const float* Wk2  = (const float*)d_in[15];
    const float* Wv2  = (const float*)d_in[16];
    const float* Wo2  = (const float*)d_in[17];
    const float* bo2  = (const float*)d_in[18];
    const float* Wff1 = (const float*)d_in[19];
    const float* bff1 = (const float*)d_in[20];
    const float* Wff2 = (const float*)d_in[21];
    const float* bff2 = (const float*)d_in[22];
    const int*   ufca = (const int*)d_in[23];
    float* out = (float*)d_out;

    float *h, *q, *k, *v, *o, *kc, *vc, *sim, *ff, *gg, *pacc, *pml;
    cudaGetSymbolAddress((void**)&h,  g_h);
    cudaGetSymbolAddress((void**)&q,  g_q);
    cudaGetSymbolAddress((void**)&k,  g_k);
    cudaGetSymbolAddress((void**)&v,  g_v);
    cudaGetSymbolAddress((void**)&o,  g_o);
    cudaGetSymbolAddress((void**)&kc, g_kc);
    cudaGetSymbolAddress((void**)&vc, g_vc);
    cudaGetSymbolAddress((void**)&sim, g_sim);
    cudaGetSymbolAddress((void**)&ff, g_ff);
    cudaGetSymbolAddress((void**)&gg, g_gg);
    cudaGetSymbolAddress((void**)&pacc, g_pacc);
    cudaGetSymbolAddress((void**)&pml, g_pml);

    dim3 g_mm(DIM / 64, N_TOK / 128, 1);
    dim3 g_qkv(DIM / 64, N_TOK / 128, 3);
    dim3 g_ctx2(DIM / 64, 1, 2);
    dim3 g_ff1(2 * FF_INNER / 64, N_TOK / 128, 1);

    // --- block 1: self-attention ---
    ln_kernel<<<N_TOK, 128>>>(x, g1, b1, h);
    sgemm_kernel<false, false><<<g_qkv, 256>>>(h, Wq1, Wk1, Wv1, nullptr, nullptr,
                                               q, k, v, N_TOK, DIM, DIM);
    self_attn_kernel<<<dim3(N_TOK / 128, HEADS, NSPLIT), 128>>>(q, k, v, pacc, pml);
    attn_combine_kernel<<<QH / 128, 128>>>(pacc, pml, o);
    sgemm_kernel<true, true><<<g_mm, 256>>>(o, Wo1, Wo1, Wo1, bo1, x,
                                            out, out, out, N_TOK, DIM, DIM);

    // --- block 2: cross-attention with FCA ---
    ln_kernel<<<N_TOK, 128>>>(out, g2, b2, h);
    sgemm_kernel<false, false><<<g_mm, 256>>>(h, Wq2, Wq2, Wq2, nullptr, nullptr,
                                              q, q, q, N_TOK, DIM, DIM);
    sgemm_kernel<false, false><<<g_ctx2, 256>>>(ctx, Wk2, Wv2, Wv2, nullptr, nullptr,
                                                kc, vc, vc, M_CTX, DIM, CTX_DIM);
    cross_scores_kernel<<<dim3(N_TOK / 128, HEADS), 128>>>(q, kc, sim);
    fca_softmax_kernel<<<dim3(N_TOK / 16, HEADS), 128>>>(sim, fam, ufca);
    cross_av_kernel<<<dim3(N_TOK / 128, HEADS), 128>>>(sim, vc, o);
    sgemm_kernel<true, true><<<g_mm, 256>>>(o, Wo2, Wo2, Wo2, bo2, out,
                                            out, out, out, N_TOK, DIM, DIM);

    // --- block 3: GEGLU feed-forward ---
    ln_kernel<<<N_TOK, 128>>>(out, g3, b3, h);
    sgemm_kernel<true, false><<<g_ff1, 256>>>(h, Wff1, Wff1, Wff1, bff1, nullptr,
                                              ff, ff, ff, N_TOK, 2 * FF_INNER, DIM);
    geglu_kernel<<<(N_TOK * FF_INNER + 255) / 256, 256>>>(ff, gg);
    sgemm_kernel<true, true><<<g_mm, 256>>>(gg, Wff2, Wff2, Wff2, bff2, out,
                                            out, out, out, N_TOK, DIM, FF_INNER);
}

// round 4
// speedup vs baseline: 1.9232x; 1.4423x over previous
#include <cuda_runtime.h>
#include <math.h>
#include <stdint.h>

#define N_TOK 4096
#define DIM 320
#define HEADS 8
#define DHEAD 40
#define CTX_DIM 768
#define M_CTX 77
#define FF_INNER 1280
#define SIM_STRIDE 80
#define SCALE 0.15811388300841898f

typedef unsigned long long ull;

// ---------------- f32x2 packed-math helpers (Blackwell FFMA2) ----------------
__device__ __forceinline__ ull dup2(float x) {
    ull r; asm("mov.b64 %0, {%1, %1};" : "=l"(r) : "f"(x)); return r;
}
__device__ __forceinline__ void fma2(ull& d, ull a, ull b) {
    asm("fma.rn.f32x2 %0, %1, %2, %0;" : "+l"(d) : "l"(a), "l"(b));
}
__device__ __forceinline__ ull mul2(ull a, ull b) {
    ull r; asm("mul.rn.f32x2 %0, %1, %2;" : "=l"(r) : "l"(a), "l"(b)); return r;
}
__device__ __forceinline__ ull add2(ull a, ull b) {
    ull r; asm("add.rn.f32x2 %0, %1, %2;" : "=l"(r) : "l"(a), "l"(b)); return r;
}
__device__ __forceinline__ float2 unpack2(ull v) {
    float2 r; asm("mov.b64 {%0, %1}, %2;" : "=f"(r.x), "=f"(r.y) : "l"(v)); return r;
}
__device__ __forceinline__ float hadd2(ull v) {
    float2 r = unpack2(v); return r.x + r.y;
}

// ---------------- tf32 m16n8k8 mma -------------------------------------------
__device__ __forceinline__ void mma_tf32(float* d, const uint32_t* a, const uint32_t* b) {
    asm volatile("mma.sync.aligned.m16n8k8.row.col.f32.tf32.tf32.f32 "
        "{%0,%1,%2,%3}, {%4,%5,%6,%7}, {%8,%9}, {%0,%1,%2,%3};"
        : "+f"(d[0]), "+f"(d[1]), "+f"(d[2]), "+f"(d[3])
        : "r"(a[0]), "r"(a[1]), "r"(a[2]), "r"(a[3]), "r"(b[0]), "r"(b[1]));
}

// ---------------- scratch (device globals; no allocation allowed) ------------
__device__ float g_h[N_TOK * DIM];
__device__ float g_q[N_TOK * DIM];
__device__ float g_k[N_TOK * DIM];
__device__ float g_v[N_TOK * DIM];
__device__ float g_o[N_TOK * DIM];
__device__ float g_kc[M_CTX * DIM];
__device__ float g_vc[M_CTX * DIM];
__device__ float g_sim[HEADS * N_TOK * SIM_STRIDE];
__device__ float g_ff[N_TOK * 2 * FF_INNER];
__device__ float g_gg[N_TOK * FF_INNER];

// ---------------- LayerNorm ---------------------------------------------------
__global__ __launch_bounds__(128) void ln_kernel(const float* __restrict__ x,
                                                 const float* __restrict__ g,
                                                 const float* __restrict__ b,
                                                 float* __restrict__ out) {
    int row = blockIdx.x;
    const float* xr = x + row * DIM;
    float s = 0.f, s2 = 0.f;
    for (int i = threadIdx.x; i < DIM; i += 128) {
        float v = xr[i];
        s += v; s2 += v * v;
    }
    #pragma unroll
    for (int off = 16; off; off >>= 1) {
        s  += __shfl_xor_sync(~0u, s, off);
        s2 += __shfl_xor_sync(~0u, s2, off);
    }
    __shared__ float rs[4], rs2[4];
    int w = threadIdx.x >> 5, lane = threadIdx.x & 31;
    if (lane == 0) { rs[w] = s; rs2[w] = s2; }
    __syncthreads();
    s  = rs[0] + rs[1] + rs[2] + rs[3];
    s2 = rs2[0] + rs2[1] + rs2[2] + rs2[3];
    float mu = s * (1.f / DIM);
    float var = s2 * (1.f / DIM) - mu * mu;
    float rstd = rsqrtf(var + 1e-5f);
    float* orow = out + row * DIM;
    for (int i = threadIdx.x; i < DIM; i += 128)
        orow[i] = (xr[i] - mu) * rstd * g[i] + b[i];
}

// ---------------- SGEMM 128x64x16, double-buffered, f32x2 ----------------------
template <bool BIAS, bool RES>
__global__ __launch_bounds__(256) void sgemm_kernel(
    const float* __restrict__ A,
    const float* B0, const float* B1, const float* B2,
    const float* __restrict__ bias, const float* __restrict__ res,
    float* C0, float* C1, float* C2,
    int M, int N, int K)
{
    const float* __restrict__ B = (blockIdx.z == 0) ? B0 : (blockIdx.z == 1 ? B1 : B2);
    float* __restrict__ C       = (blockIdx.z == 0) ? C0 : (blockIdx.z == 1 ? C1 : C2);

    __shared__ float As[2][16][132];
    __shared__ float Bs[2][16][64];

    int t = threadIdx.x;
    int tx = t & 15, ty = t >> 4;
    int bm = blockIdx.y * 128, bn = blockIdx.x * 64;
    int m0 = ty * 8, n0 = tx * 4;

    int a_row0 = t >> 2;
    int a_row1 = a_row0 + 64;
    int a_kg = (t & 3) * 4;
    int b_kk = t >> 4, b_nc = (t & 15) * 4;
    int gm0 = bm + a_row0, gm1 = bm + a_row1;

    ull acc[4][4];
    #pragma unroll
    for (int p = 0; p < 4; p++)
        #pragma unroll
        for (int n = 0; n < 4; n++) acc[p][n] = 0ull;

    float4 aR0, aR1, bR;
    aR0 = (gm0 < M) ? *(const float4*)(A + (size_t)gm0 * K + a_kg) : make_float4(0.f,0.f,0.f,0.f);
    aR1 = (gm1 < M) ? *(const float4*)(A + (size_t)gm1 * K + a_kg) : make_float4(0.f,0.f,0.f,0.f);
    bR  = *(const float4*)(B + (size_t)b_kk * N + bn + b_nc);
    As[0][a_kg + 0][a_row0] = aR0.x; As[0][a_kg + 1][a_row0] = aR0.y;
    As[0][a_kg + 2][a_row0] = aR0.z; As[0][a_kg + 3][a_row0] = aR0.w;
    As[0][a_kg + 0][a_row1] = aR1.x; As[0][a_kg + 1][a_row1] = aR1.y;
    As[0][a_kg + 2][a_row1] = aR1.z; As[0][a_kg + 3][a_row1] = aR1.w;
    *(float4*)&Bs[0][b_kk][b_nc] = bR;
    __syncthreads();

    int nt = K >> 4;
    for (int it = 0; it < nt; it++) {
        int cur = it & 1;
        if (it + 1 < nt) {
            int k0 = (it + 1) << 4;
            aR0 = (gm0 < M) ? *(const float4*)(A + (size_t)gm0 * K + k0 + a_kg) : make_float4(0.f,0.f,0.f,0.f);
            aR1 = (gm1 < M) ? *(const float4*)(A + (size_t)gm1 * K + k0 + a_kg) : make_float4(0.f,0.f,0.f,0.f);
            bR  = *(const float4*)(B + (size_t)(k0 + b_kk) * N + bn + b_nc);
        }
        #pragma unroll
        for (int kk = 0; kk < 16; kk++) {
            ulonglong2 a01 = *(const ulonglong2*)&As[cur][kk][m0];
            ulonglong2 a23 = *(const ulonglong2*)&As[cur][kk][m0 + 4];
            float4 bv = *(const float4*)&Bs[cur][kk][n0];
            ull bd0 = dup2(bv.x), bd1 = dup2(bv.y), bd2 = dup2(bv.z), bd3 = dup2(bv.w);
            fma2(acc[0][0], a01.x, bd0); fma2(acc[0][1], a01.x, bd1);
            fma2(acc[0][2], a01.x, bd2); fma2(acc[0][3], a01.x, bd3);
            fma2(acc[1][0], a01.y, bd0); fma2(acc[1][1], a01.y, bd1);
            fma2(acc[1][2], a01.y, bd2); fma2(acc[1][3], a01.y, bd3);
            fma2(acc[2][0], a23.x, bd0); fma2(acc[2][1], a23.x, bd1);
            fma2(acc[2][2], a23.x, bd2); fma2(acc[2][3], a23.x, bd3);
            fma2(acc[3][0], a23.y, bd0); fma2(acc[3][1], a23.y, bd1);
            fma2(acc[3][2], a23.y, bd2); fma2(acc[3][3], a23.y, bd3);
        }
        if (it + 1 < nt) {
            int nxt = cur ^ 1;
            As[nxt][a_kg + 0][a_row0] = aR0.x; As[nxt][a_kg + 1][a_row0] = aR0.y;
            As[nxt][a_kg + 2][a_row0] = aR0.z; As[nxt][a_kg + 3][a_row0] = aR0.w;
            As[nxt][a_kg + 0][a_row1] = aR1.x; As[nxt][a_kg + 1][a_row1] = aR1.y;
            As[nxt][a_kg + 2][a_row1] = aR1.z; As[nxt][a_kg + 3][a_row1] = aR1.w;
            *(float4*)&Bs[nxt][b_kk][b_nc] = bR;
        }
        __syncthreads();
    }

    int gn = bn + n0;
    float4 bsv = make_float4(0.f, 0.f, 0.f, 0.f);
    if (BIAS) bsv = *(const float4*)&bias[gn];
    #pragma unroll
    for (int p = 0; p < 4; p++) {
        float2 c0 = unpack2(acc[p][0]), c1 = unpack2(acc[p][1]);
        float2 c2 = unpack2(acc[p][2]), c3 = unpack2(acc[p][3]);
        float4 rlo = make_float4(c0.x + bsv.x, c1.x + bsv.y, c2.x + bsv.z, c3.x + bsv.w);
        float4 rhi = make_float4(c0.y + bsv.x, c1.y + bsv.y, c2.y + bsv.z, c3.y + bsv.w);
        int gm_lo = bm + m0 + 2 * p;
        if (gm_lo < M) {
            if (RES) {
                float4 rv = *(const float4*)(res + (size_t)gm_lo * N + gn);
                rlo.x += rv.x; rlo.y += rv.y; rlo.z += rv.z; rlo.w += rv.w;
            }
            *(float4*)(C + (size_t)gm_lo * N + gn) = rlo;
        }
        if (gm_lo + 1 < M) {
            if (RES) {
                float4 rv = *(const float4*)(res + (size_t)(gm_lo + 1) * N + gn);
                rhi.x += rv.x; rhi.y += rv.y; rhi.z += rv.z; rhi.w += rv.w;
            }
            *(float4*)(C + (size_t)(gm_lo + 1) * N + gn) = rhi;
        }
    }
}

// ---------------- self-attention: tf32 mma flash --------------------------------
// Block: 128 queries x 1 head. 4 warps, each warp owns 32 queries (2 m16 tiles).
// Keys streamed in 64-key tiles.
__global__ __launch_bounds__(128) void self_attn_mma_kernel(
    const float* __restrict__ q, const float* __restrict__ k,
    const float* __restrict__ v, float* __restrict__ out)
{
    __shared__ float Ks[64][44];
    __shared__ float Vs[64][44];
    __shared__ float Ps[4][16][72];

    int tid = threadIdx.x;
    int w = tid >> 5, lane = tid & 31;
    int gid = lane >> 2, tig = lane & 3;
    int head = blockIdx.y;
    int qbase = blockIdx.x * 128 + w * 32;

    // Q a-fragments (tf32 as raw fp32 bits), pre-scaled
    uint32_t qa[2][5][4];
    #pragma unroll
    for (int mt = 0; mt < 2; mt++) {
        const float* q0 = q + (size_t)(qbase + mt * 16 + gid) * DIM + head * DHEAD;
        const float* q1 = q0 + 8 * DIM;
        #pragma unroll
        for (int ks = 0; ks < 5; ks++) {
            qa[mt][ks][0] = __float_as_uint(q0[ks * 8 + tig] * SCALE);
            qa[mt][ks][1] = __float_as_uint(q1[ks * 8 + tig] * SCALE);
            qa[mt][ks][2] = __float_as_uint(q0[ks * 8 + tig + 4] * SCALE);
            qa[mt][ks][3] = __float_as_uint(q1[ks * 8 + tig + 4] * SCALE);
        }
    }

    float o[2][5][4];
    #pragma unroll
    for (int mt = 0; mt < 2; mt++)
        #pragma unroll
        for (int n = 0; n < 5; n++)
            #pragma unroll
            for (int i = 0; i < 4; i++) o[mt][n][i] = 0.f;
    float mrow[2][2], lrow[2][2];
    #pragma unroll
    for (int mt = 0; mt < 2; mt++) {
        mrow[mt][0] = -1e30f; mrow[mt][1] = -1e30f;
        lrow[mt][0] = 0.f;    lrow[mt][1] = 0.f;
    }

    for (int kt = 0; kt < N_TOK; kt += 64) {
        __syncthreads();
        #pragma unroll
        for (int it = 0; it < 5; it++) {
            int idx = tid + it * 128;
            int row = idx / 10, c = idx % 10;
            size_t goff = (size_t)(kt + row) * DIM + head * DHEAD + c * 4;
            *(float4*)&Ks[row][c * 4] = *(const float4*)(k + goff);
            *(float4*)&Vs[row][c * 4] = *(const float4*)(v + goff);
        }
        __syncthreads();

        #pragma unroll
        for (int mt = 0; mt < 2; mt++) {
            // ---- S = Q K^T for this m16 tile: 8 n-tiles x 5 k-steps ----
            float c[8][4];
            #pragma unroll
            for (int j = 0; j < 8; j++) {
                c[j][0] = 0.f; c[j][1] = 0.f; c[j][2] = 0.f; c[j][3] = 0.f;
                #pragma unroll
                for (int ks = 0; ks < 5; ks++) {
                    uint32_t b[2];
                    b[0] = __float_as_uint(Ks[j * 8 + gid][ks * 8 + tig]);
                    b[1] = __float_as_uint(Ks[j * 8 + gid][ks * 8 + tig + 4]);
                    mma_tf32(c[j], qa[mt][ks], b);
                }
            }
            // ---- online softmax over this 64-key tile ----
            float mx0 = -1e30f, mx1 = -1e30f;
            #pragma unroll
            for (int j = 0; j < 8; j++) {
                mx0 = fmaxf(mx0, fmaxf(c[j][0], c[j][1]));
                mx1 = fmaxf(mx1, fmaxf(c[j][2], c[j][3]));
            }
            mx0 = fmaxf(mx0, __shfl_xor_sync(~0u, mx0, 1));
            mx0 = fmaxf(mx0, __shfl_xor_sync(~0u, mx0, 2));
            mx1 = fmaxf(mx1, __shfl_xor_sync(~0u, mx1, 1));
            mx1 = fmaxf(mx1, __shfl_xor_sync(~0u, mx1, 2));
            float mn0 = fmaxf(mrow[mt][0], mx0);
            float mn1 = fmaxf(mrow[mt][1], mx1);
            float cor0 = __expf(mrow[mt][0] - mn0);
            float cor1 = __expf(mrow[mt][1] - mn1);
            mrow[mt][0] = mn0; mrow[mt][1] = mn1;
            float sum0 = 0.f, sum1 = 0.f;
            #pragma unroll
            for (int j = 0; j < 8; j++) {
                c[j][0] = __expf(c[j][0] - mn0);
                c[j][1] = __expf(c[j][1] - mn0);
                c[j][2] = __expf(c[j][2] - mn1);
                c[j][3] = __expf(c[j][3] - mn1);
                sum0 += c[j][0] + c[j][1];
                sum1 += c[j][2] + c[j][3];
            }
            sum0 += __shfl_xor_sync(~0u, sum0, 1);
            sum0 += __shfl_xor_sync(~0u, sum0, 2);
            sum1 += __shfl_xor_sync(~0u, sum1, 1);
            sum1 += __shfl_xor_sync(~0u, sum1, 2);
            lrow[mt][0] = lrow[mt][0] * cor0 + sum0;
            lrow[mt][1] = lrow[mt][1] * cor1 + sum1;
            #pragma unroll
            for (int n = 0; n < 5; n++) {
                o[mt][n][0] *= cor0; o[mt][n][1] *= cor0;
                o[mt][n][2] *= cor1; o[mt][n][3] *= cor1;
            }
            // ---- write P to per-warp smem (c-layout -> a-layout bridge) ----
            __syncwarp();
            #pragma unroll
            for (int j = 0; j < 8; j++) {
                *(float2*)&Ps[w][gid][j * 8 + 2 * tig]     = make_float2(c[j][0], c[j][1]);
                *(float2*)&Ps[w][gid + 8][j * 8 + 2 * tig] = make_float2(c[j][2], c[j][3]);
            }
            __syncwarp();
            // ---- O += P V ----
            #pragma unroll
            for (int kk = 0; kk < 8; kk++) {
                uint32_t pa[4];
                pa[0] = __float_as_uint(Ps[w][gid][kk * 8 + tig]);
                pa[1] = __float_as_uint(Ps[w][gid + 8][kk * 8 + tig]);
                pa[2] = __float_as_uint(Ps[w][gid][kk * 8 + tig + 4]);
                pa[3] = __float_as_uint(Ps[w][gid + 8][kk * 8 + tig + 4]);
                #pragma unroll
                for (int n = 0; n < 5; n++) {
                    uint32_t vb[2];
                    vb[0] = __float_as_uint(Vs[kk * 8 + tig][n * 8 + gid]);
                    vb[1] = __float_as_uint(Vs[kk * 8 + tig + 4][n * 8 + gid]);
                    mma_tf32(o[mt][n], pa, vb);
                }
            }
            __syncwarp();
        }
    }

    // ---- epilogue: normalize and store ----
    #pragma unroll
    for (int mt = 0; mt < 2; mt++) {
        float inv0 = 1.f / lrow[mt][0];
        float inv1 = 1.f / lrow[mt][1];
        int r0 = qbase + mt * 16 + gid;
        float* o0 = out + (size_t)r0 * DIM + head * DHEAD;
        float* o1 = o0 + 8 * DIM;
        #pragma unroll
        for (int n = 0; n < 5; n++) {
            *(float2*)(o0 + n * 8 + 2 * tig) = make_float2(o[mt][n][0] * inv0, o[mt][n][1] * inv0);
            *(float2*)(o1 + n * 8 + 2 * tig) = make_float2(o[mt][n][2] * inv1, o[mt][n][3] * inv1);
        }
    }
}

// ---------------- cross-attention scores (f32x2) --------------------------------
__global__ __launch_bounds__(128) void cross_scores_kernel(
    const float* __restrict__ q, const float* __restrict__ kc,
    float* __restrict__ sim)
{
    __shared__ ulonglong2 Ks[M_CTX * 10];
    int head = blockIdx.y;
    int qi = blockIdx.x * 128 + threadIdx.x;
    for (int idx = threadIdx.x; idx < M_CTX * 10; idx += 128) {
        int row = idx / 10, c = idx % 10;
        Ks[idx] = *(const ulonglong2*)(kc + (size_t)row * DIM + head * DHEAD + c * 4);
    }
    __syncthreads();
    ull q2[20];
    {
        const ulonglong2* qp = (const ulonglong2*)(q + (size_t)qi * DIM + head * DHEAD);
        ull sc = dup2(SCALE);
        #pragma unroll
        for (int i = 0; i < 10; i++) {
            ulonglong2 tq = qp[i];
            q2[2 * i]     = mul2(tq.x, sc);
            q2[2 * i + 1] = mul2(tq.y, sc);
        }
    }
    float* srow = sim + ((size_t)head * N_TOK + qi) * SIM_STRIDE;
    for (int j = 0; j < M_CTX; j++) {
        ull sa = 0ull, sb = 0ull;
        const ulonglong2* kr = &Ks[j * 10];
        #pragma unroll
        for (int i = 0; i < 10; i++) {
            ulonglong2 kv = kr[i];
            fma2(sa, q2[2 * i],     kv.x);
            fma2(sb, q2[2 * i + 1], kv.y);
        }
        srow[j] = hadd2(add2(sa, sb));
    }
}

// ---------------- FCA mask + softmax (16 rows/block) ----------------------------
__global__ __launch_bounds__(128) void fca_softmax_kernel(
    float* __restrict__ sim, const float* __restrict__ fam,
    const int* __restrict__ use_fca_p)
{
    __shared__ float fam_s[M_CTX * M_CTX];
    __shared__ float srow[16][M_CTX];
    int use_fca = *use_fca_p;
    int head = blockIdx.y;
    int qbase = blockIdx.x * 16;
    for (int i = threadIdx.x; i < M_CTX * M_CTX; i += 128)
        fam_s[i] = fam[i];
    for (int idx = threadIdx.x; idx < 16 * M_CTX; idx += 128) {
        int r = idx / M_CTX, d = idx - r * M_CTX;
        srow[r][d] = sim[((size_t)head * N_TOK + qbase + r) * SIM_STRIDE + d];
    }
    __syncthreads();
    int w = threadIdx.x >> 5, lane = threadIdx.x & 31;
    int dd[3] = { lane, lane + 32, lane + 64 };

    for (int rr = 0; rr < 4; rr++) {
        int r = w * 4 + rr;
        float* grow = sim + ((size_t)head * N_TOK + qbase + r) * SIM_STRIDE;
        if (use_fca != 0) {
            float f[3];
            float fmax_local = 0.f;
            #pragma unroll
            for (int t = 0; t < 3; t++) {
                f[t] = -1.f;
                int d = dd[t];
                if (d < M_CTX) {
                    float a = 0.f;
                    for (int kk = 0; kk < M_CTX; kk++)
                        a += srow[r][kk] * fam_s[d * M_CTX + kk];
                    f[t] = fminf(fabsf(a), 1.f);
                    fmax_local = fmaxf(fmax_local, f[t]);
                }
            }
            #pragma unroll
            for (int off = 16; off; off >>= 1)
                fmax_local = fmaxf(fmax_local, __shfl_xor_sync(~0u, fmax_local, off));
            float denom = fmax_local + 1e-6f;
            __syncwarp();
            #pragma unroll
            for (int t = 0; t < 3; t++) {
                int d = dd[t];
                if (d < M_CTX) {
                    float keep = (f[t] / denom > 0.6f) ? 0.f : -50.f;
                    srow[r][d] += keep;
                }
            }
            __syncwarp();
        }
        float mloc = -1e30f;
        #pragma unroll
        for (int t = 0; t < 3; t++)
            if (dd[t] < M_CTX) mloc = fmaxf(mloc, srow[r][dd[t]]);
        #pragma unroll
        for (int off = 16; off; off >>= 1)
            mloc = fmaxf(mloc, __shfl_xor_sync(~0u, mloc, off));
        float pv[3]; float ssum = 0.f;
        #pragma unroll
        for (int t = 0; t < 3; t++) {
            pv[t] = 0.f;
            if (dd[t] < M_CTX) { pv[t] = __expf(srow[r][dd[t]] - mloc); ssum += pv[t]; }
        }
        #pragma unroll
        for (int off = 16; off; off >>= 1)
            ssum += __shfl_xor_sync(~0u, ssum, off);
        float inv = 1.f / ssum;
        #pragma unroll
        for (int t = 0; t < 3; t++)
            if (dd[t] < M_CTX) grow[dd[t]] = pv[t] * inv;
    }
}

// ---------------- cross-attention AV (f32x2) -------------------------------------
__global__ __launch_bounds__(128) void cross_av_kernel(
    const float* __restrict__ sim, const float* __restrict__ vc,
    float* __restrict__ out)
{
    __shared__ ulonglong2 Vs[M_CTX * 10];
    int head = blockIdx.y;
    int qi = blockIdx.x * 128 + threadIdx.x;
    for (int idx = threadIdx.x; idx < M_CTX * 10; idx += 128) {
        int row = idx / 10, c = idx % 10;
        Vs[idx] = *(const ulonglong2*)(vc + (size_t)row * DIM + head * DHEAD + c * 4);
    }
    __syncthreads();
    const float* srow = sim + ((size_t)head * N_TOK + qi) * SIM_STRIDE;
    ull acc[20];
    #pragma unroll
    for (int i = 0; i < 20; i++) acc[i] = 0ull;
    for (int j = 0; j < M_CTX; j++) {
        ull pd = dup2(srow[j]);
        const ulonglong2* vr = &Vs[j * 10];
        #pragma unroll
        for (int i = 0; i < 10; i++) {
            ulonglong2 vv = vr[i];
            fma2(acc[2 * i],     pd, vv.x);
            fma2(acc[2 * i + 1], pd, vv.y);
        }
    }
    ulonglong2* op = (ulonglong2*)(out + (size_t)qi * DIM + head * DHEAD);
    #pragma unroll
    for (int i = 0; i < 10; i++) {
        ulonglong2 tv;
        tv.x = acc[2 * i];
        tv.y = acc[2 * i + 1];
        op[i] = tv;
    }
}

// ---------------- GEGLU ---------------------------------------------------------
__global__ __launch_bounds__(256) void geglu_kernel(const float* __restrict__ ff,
                                                    float* __restrict__ out) {
    int idx = blockIdx.x * 256 + threadIdx.x;
    if (idx >= N_TOK * FF_INNER) return;
    int row = idx / FF_INNER, col = idx - row * FF_INNER;
    float a = ff[(size_t)row * 2 * FF_INNER + col];
    float gt = ff[(size_t)row * 2 * FF_INNER + FF_INNER + col];
    float ge = 0.5f * gt * (1.f + erff(gt * 0.70710678118654752f));
    out[idx] = a * ge;
}

// ---------------- launch ---------------------------------------------------------
extern "C" void kernel_launch(void* const* d_in, const int* in_sizes, int n_in,
                              void* d_out, int out_size)
{
    const float* x    = (const float*)d_in[0];
    const float* ctx  = (const float*)d_in[1];
    const float* fam  = (const float*)d_in[2];
    const float* g1   = (const float*)d_in[3];
    const float* b1   = (const float*)d_in[4];
    const float* g2   = (const float*)d_in[5];
    const float* b2   = (const float*)d_in[6];
    const float* g3   = (const float*)d_in[7];
    const float* b3   = (const float*)d_in[8];
    const float* Wq1  = (const float*)d_in[9];
    const float* Wk1  = (const float*)d_in[10];
    const float* Wv1  = (const float*)d_in[11];
    const float* Wo1  = (const float*)d_in[12];
    const float* bo1  = (const float*)d_in[13];
    const float* Wq2  = (const float*)d_in[14];
    const float* Wk2  = (const float*)d_in[15];
    const float* Wv2  = (const float*)d_in[16];
    const float* Wo2  = (const float*)d_in[17];
    const float* bo2  = (const float*)d_in[18];
    const float* Wff1 = (const float*)d_in[19];
    const float* bff1 = (const float*)d_in[20];
    const float* Wff2 = (const float*)d_in[21];
    const float* bff2 = (const float*)d_in[22];
    const int*   ufca = (const int*)d_in[23];
    float* out = (float*)d_out;

    float *h, *q, *k, *v, *o, *kc, *vc, *sim, *ff, *gg;
    cudaGetSymbolAddress((void**)&h,  g_h);
    cudaGetSymbolAddress((void**)&q,  g_q);
    cudaGetSymbolAddress((void**)&k,  g_k);
    cudaGetSymbolAddress((void**)&v,  g_v);
    cudaGetSymbolAddress((void**)&o,  g_o);
    cudaGetSymbolAddress((void**)&kc, g_kc);
    cudaGetSymbolAddress((void**)&vc, g_vc);
    cudaGetSymbolAddress((void**)&sim, g_sim);
    cudaGetSymbolAddress((void**)&ff, g_ff);
    cudaGetSymbolAddress((void**)&gg, g_gg);

    dim3 g_mm(DIM / 64, N_TOK / 128, 1);
    dim3 g_qkv(DIM / 64, N_TOK / 128, 3);
    dim3 g_ctx2(DIM / 64, 1, 2);
    dim3 g_ff1(2 * FF_INNER / 64, N_TOK / 128, 1);

    // --- block 1: self-attention ---
    ln_kernel<<<N_TOK, 128>>>(x, g1, b1, h);
    sgemm_kernel<false, false><<<g_qkv, 256>>>(h, Wq1, Wk1, Wv1, nullptr, nullptr,
                                               q, k, v, N_TOK, DIM, DIM);
    self_attn_mma_kernel<<<dim3(N_TOK / 128, HEADS), 128>>>(q, k, v, o);
    sgemm_kernel<true, true><<<g_mm, 256>>>(o, Wo1, Wo1, Wo1, bo1, x,
                                            out, out, out, N_TOK, DIM, DIM);

    // --- block 2: cross-attention with FCA ---
    ln_kernel<<<N_TOK, 128>>>(out, g2, b2, h);
    sgemm_kernel<false, false><<<g_mm, 256>>>(h, Wq2, Wq2, Wq2, nullptr, nullptr,
                                              q, q, q, N_TOK, DIM, DIM);
    sgemm_kernel<false, false><<<g_ctx2, 256>>>(ctx, Wk2, Wv2, Wv2, nullptr, nullptr,
                                                kc, vc, vc, M_CTX, DIM, CTX_DIM);
    cross_scores_kernel<<<dim3(N_TOK / 128, HEADS), 128>>>(q, kc, sim);
    fca_softmax_kernel<<<dim3(N_TOK / 16, HEADS), 128>>>(sim, fam, ufca);
    cross_av_kernel<<<dim3(N_TOK / 128, HEADS), 128>>>(sim, vc, o);
    sgemm_kernel<true, true><<<g_mm, 256>>>(o, Wo2, Wo2, Wo2, bo2, out,
                                            out, out, out, N_TOK, DIM, DIM);

    // --- block 3: GEGLU feed-forward ---
    ln_kernel<<<N_TOK, 128>>>(out, g3, b3, h);
    sgemm_kernel<true, false><<<g_ff1, 256>>>(h, Wff1, Wff1, Wff1, bff1, nullptr,
                                              ff, ff, ff, N_TOK, 2 * FF_INNER, DIM);
    geglu_kernel<<<(N_TOK * FF_INNER + 255) / 256, 256>>>(ff, gg);
    sgemm_kernel<true, true><<<g_mm, 256>>>(gg, Wff2, Wff2, Wff2, bff2, out,
                                            out, out, out, N_TOK, DIM, FF_INNER);
}

// round 6
// speedup vs baseline: 2.1487x; 1.1173x over previous
#include <cuda_runtime.h>
#include <math.h>
#include <stdint.h>

#define N_TOK 4096
#define DIM 320
#define HEADS 8
#define DHEAD 40
#define CTX_DIM 768
#define M_CTX 77
#define FF_INNER 1280
#define SIM_STRIDE 80
#define SCALE 0.15811388300841898f

typedef unsigned long long ull;

// ---------------- f32x2 packed-math helpers ----------------
__device__ __forceinline__ ull dup2(float x) {
    ull r; asm("mov.b64 %0, {%1, %1};" : "=l"(r) : "f"(x)); return r;
}
__device__ __forceinline__ void fma2(ull& d, ull a, ull b) {
    asm("fma.rn.f32x2 %0, %1, %2, %0;" : "+l"(d) : "l"(a), "l"(b));
}
__device__ __forceinline__ ull mul2(ull a, ull b) {
    ull r; asm("mul.rn.f32x2 %0, %1, %2;" : "=l"(r) : "l"(a), "l"(b)); return r;
}
__device__ __forceinline__ ull add2(ull a, ull b) {
    ull r; asm("add.rn.f32x2 %0, %1, %2;" : "=l"(r) : "l"(a), "l"(b)); return r;
}
__device__ __forceinline__ float2 unpack2(ull v) {
    float2 r; asm("mov.b64 {%0, %1}, %2;" : "=f"(r.x), "=f"(r.y) : "l"(v)); return r;
}
__device__ __forceinline__ float hadd2(ull v) {
    float2 r = unpack2(v); return r.x + r.y;
}

// ---------------- tf32 m16n8k8 mma -------------------------------------------
__device__ __forceinline__ void mma_tf32(float* d, const uint32_t* a, const uint32_t* b) {
    asm volatile("mma.sync.aligned.m16n8k8.row.col.f32.tf32.tf32.f32 "
        "{%0,%1,%2,%3}, {%4,%5,%6,%7}, {%8,%9}, {%0,%1,%2,%3};"
        : "+f"(d[0]), "+f"(d[1]), "+f"(d[2]), "+f"(d[3])
        : "r"(a[0]), "r"(a[1]), "r"(a[2]), "r"(a[3]), "r"(b[0]), "r"(b[1]));
}

// split fp32 -> tf32 hi + residual lo (3xTF32 scheme)
__device__ __forceinline__ void split_tf32(float x, uint32_t& hi, uint32_t& lo) {
    uint32_t h;
    asm("cvt.rna.tf32.f32 %0, %1;" : "=r"(h) : "f"(x));
    hi = h;
    lo = __float_as_uint(x - __uint_as_float(h));
}

// ---------------- scratch (device globals; no allocation allowed) ------------
__device__ float g_h[N_TOK * DIM];
__device__ float g_q[N_TOK * DIM];
__device__ float g_k[N_TOK * DIM];
__device__ float g_v[N_TOK * DIM];
__device__ float g_o[N_TOK * DIM];
__device__ float g_kc[M_CTX * DIM];
__device__ float g_vc[M_CTX * DIM];
__device__ float g_sim[HEADS * N_TOK * SIM_STRIDE];
__device__ float g_ff[N_TOK * 2 * FF_INNER];
__device__ float g_gg[N_TOK * FF_INNER];

// ---------------- LayerNorm ---------------------------------------------------
__global__ __launch_bounds__(128) void ln_kernel(const float* __restrict__ x,
                                                 const float* __restrict__ g,
                                                 const float* __restrict__ b,
                                                 float* __restrict__ out) {
    int row = blockIdx.x;
    const float* xr = x + row * DIM;
    float s = 0.f, s2 = 0.f;
    for (int i = threadIdx.x; i < DIM; i += 128) {
        float v = xr[i];
        s += v; s2 += v * v;
    }
    #pragma unroll
    for (int off = 16; off; off >>= 1) {
        s  += __shfl_xor_sync(~0u, s, off);
        s2 += __shfl_xor_sync(~0u, s2, off);
    }
    __shared__ float rs[4], rs2[4];
    int w = threadIdx.x >> 5, lane = threadIdx.x & 31;
    if (lane == 0) { rs[w] = s; rs2[w] = s2; }
    __syncthreads();
    s  = rs[0] + rs[1] + rs[2] + rs[3];
    s2 = rs2[0] + rs2[1] + rs2[2] + rs2[3];
    float mu = s * (1.f / DIM);
    float var = s2 * (1.f / DIM) - mu * mu;
    float rstd = rsqrtf(var + 1e-5f);
    float* orow = out + row * DIM;
    for (int i = threadIdx.x; i < DIM; i += 128)
        orow[i] = (xr[i] - mu) * rstd * g[i] + b[i];
}

// ---------------- 3xTF32 tensor-core GEMM 128x64, warp 32x32 -------------------
// z-batched: blockIdx.z selects (B, C) pair.
template <bool BIAS, bool RES>
__global__ __launch_bounds__(256) void tgemm_kernel(
    const float* __restrict__ A,
    const float* B0, const float* B1, const float* B2,
    const float* __restrict__ bias, const float* __restrict__ res,
    float* C0, float* C1, float* C2,
    int M, int N, int K)
{
    const float* __restrict__ B = (blockIdx.z == 0) ? B0 : (blockIdx.z == 1 ? B1 : B2);
    float* __restrict__ C       = (blockIdx.z == 0) ? C0 : (blockIdx.z == 1 ? C1 : C2);

    __shared__ float As[2][128][20];   // [m][k], pitch 20 -> conflict-free a-frag LDS
    __shared__ float Bs[2][16][72];    // [k][n], pitch 72 -> conflict-free b-frag LDS

    int t = threadIdx.x;
    int w = t >> 5, lane = t & 31;
    int gid = lane >> 2, tig = lane & 3;
    int wm = (w >> 1) * 32, wn = (w & 1) * 32;
    int bm = blockIdx.y * 128, bn = blockIdx.x * 64;

    int a_row0 = t >> 2;
    int a_row1 = a_row0 + 64;
    int a_kq = (t & 3) * 4;
    int b_k = t >> 4;
    int b_n = (t & 15) * 4;
    int gm0 = bm + a_row0, gm1 = bm + a_row1;

    float acc[2][4][4];
    #pragma unroll
    for (int mt = 0; mt < 2; mt++)
        #pragma unroll
        for (int nt = 0; nt < 4; nt++)
            #pragma unroll
            for (int i = 0; i < 4; i++) acc[mt][nt][i] = 0.f;

    float4 aR0, aR1, bR;
    const float4 z4 = make_float4(0.f, 0.f, 0.f, 0.f);
    aR0 = (gm0 < M) ? *(const float4*)(A + (size_t)gm0 * K + a_kq) : z4;
    aR1 = (gm1 < M) ? *(const float4*)(A + (size_t)gm1 * K + a_kq) : z4;
    bR  = *(const float4*)(B + (size_t)b_k * N + bn + b_n);
    *(float4*)&As[0][a_row0][a_kq] = aR0;
    *(float4*)&As[0][a_row1][a_kq] = aR1;
    *(float4*)&Bs[0][b_k][b_n] = bR;
    __syncthreads();

    int nt_chunks = K >> 4;
    for (int it = 0; it < nt_chunks; it++) {
        int cur = it & 1;
        if (it + 1 < nt_chunks) {
            int k0 = (it + 1) << 4;
            aR0 = (gm0 < M) ? *(const float4*)(A + (size_t)gm0 * K + k0 + a_kq) : z4;
            aR1 = (gm1 < M) ? *(const float4*)(A + (size_t)gm1 * K + k0 + a_kq) : z4;
            bR  = *(const float4*)(B + (size_t)(k0 + b_k) * N + bn + b_n);
        }
        #pragma unroll
        for (int ks = 0; ks < 2; ks++) {
            uint32_t ah[2][4], al[2][4];
            #pragma unroll
            for (int mt = 0; mt < 2; mt++) {
                int r = wm + mt * 16 + gid;
                split_tf32(As[cur][r][ks * 8 + tig],         ah[mt][0], al[mt][0]);
                split_tf32(As[cur][r + 8][ks * 8 + tig],     ah[mt][1], al[mt][1]);
                split_tf32(As[cur][r][ks * 8 + tig + 4],     ah[mt][2], al[mt][2]);
                split_tf32(As[cur][r + 8][ks * 8 + tig + 4], ah[mt][3], al[mt][3]);
            }
            uint32_t bh[4][2], bl[4][2];
            #pragma unroll
            for (int nt = 0; nt < 4; nt++) {
                int col = wn + nt * 8 + gid;
                split_tf32(Bs[cur][ks * 8 + tig][col],     bh[nt][0], bl[nt][0]);
                split_tf32(Bs[cur][ks * 8 + tig + 4][col], bh[nt][1], bl[nt][1]);
            }
            #pragma unroll
            for (int mt = 0; mt < 2; mt++)
                #pragma unroll
                for (int nt = 0; nt < 4; nt++) {
                    mma_tf32(acc[mt][nt], al[mt], bh[nt]);
                    mma_tf32(acc[mt][nt], ah[mt], bl[nt]);
                    mma_tf32(acc[mt][nt], ah[mt], bh[nt]);
                }
        }
        if (it + 1 < nt_chunks) {
            int nxt = cur ^ 1;
            *(float4*)&As[nxt][a_row0][a_kq] = aR0;
            *(float4*)&As[nxt][a_row1][a_kq] = aR1;
            *(float4*)&Bs[nxt][b_k][b_n] = bR;
        }
        __syncthreads();
    }

    #pragma unroll
    for (int mt = 0; mt < 2; mt++) {
        int r0 = bm + wm + mt * 16 + gid;
        int r1 = r0 + 8;
        #pragma unroll
        for (int nt = 0; nt < 4; nt++) {
            int col = bn + wn + nt * 8 + 2 * tig;
            float2 bv = make_float2(0.f, 0.f);
            if (BIAS) bv = *(const float2*)&bias[col];
            float2 lo = make_float2(acc[mt][nt][0] + bv.x, acc[mt][nt][1] + bv.y);
            float2 hi = make_float2(acc[mt][nt][2] + bv.x, acc[mt][nt][3] + bv.y);
            if (r0 < M) {
                if (RES) {
                    float2 rv = *(const float2*)(res + (size_t)r0 * N + col);
                    lo.x += rv.x; lo.y += rv.y;
                }
                *(float2*)(C + (size_t)r0 * N + col) = lo;
            }
            if (r1 < M) {
                if (RES) {
                    float2 rv = *(const float2*)(res + (size_t)r1 * N + col);
                    hi.x += rv.x; hi.y += rv.y;
                }
                *(float2*)(C + (size_t)r1 * N + col) = hi;
            }
        }
    }
}

// ---------------- self-attention: tf32 mma flash --------------------------------
__global__ __launch_bounds__(128) void self_attn_mma_kernel(
    const float* __restrict__ q, const float* __restrict__ k,
    const float* __restrict__ v, float* __restrict__ out)
{
    __shared__ float Ks[64][44];
    __shared__ float Vs[64][44];
    __shared__ float Ps[4][16][72];

    int tid = threadIdx.x;
    int w = tid >> 5, lane = tid & 31;
    int gid = lane >> 2, tig = lane & 3;
    int head = blockIdx.y;
    int qbase = blockIdx.x * 128 + w * 32;

    uint32_t qa[2][5][4];
    #pragma unroll
    for (int mt = 0; mt < 2; mt++) {
        const float* q0 = q + (size_t)(qbase + mt * 16 + gid) * DIM + head * DHEAD;
        const float* q1 = q0 + 8 * DIM;
        #pragma unroll
        for (int ks = 0; ks < 5; ks++) {
            qa[mt][ks][0] = __float_as_uint(q0[ks * 8 + tig] * SCALE);
            qa[mt][ks][1] = __float_as_uint(q1[ks * 8 + tig] * SCALE);
            qa[mt][ks][2] = __float_as_uint(q0[ks * 8 + tig + 4] * SCALE);
            qa[mt][ks][3] = __float_as_uint(q1[ks * 8 + tig + 4] * SCALE);
        }
    }

    float o[2][5][4];
    #pragma unroll
    for (int mt = 0; mt < 2; mt++)
        #pragma unroll
        for (int n = 0; n < 5; n++)
            #pragma unroll
            for (int i = 0; i < 4; i++) o[mt][n][i] = 0.f;
    float mrow[2][2], lrow[2][2];
    #pragma unroll
    for (int mt = 0; mt < 2; mt++) {
        mrow[mt][0] = -1e30f; mrow[mt][1] = -1e30f;
        lrow[mt][0] = 0.f;    lrow[mt][1] = 0.f;
    }

    for (int kt = 0; kt < N_TOK; kt += 64) {
        __syncthreads();
        #pragma unroll
        for (int it = 0; it < 5; it++) {
            int idx = tid + it * 128;
            int row = idx / 10, c = idx % 10;
            size_t goff = (size_t)(kt + row) * DIM + head * DHEAD + c * 4;
            *(float4*)&Ks[row][c * 4] = *(const float4*)(k + goff);
            *(float4*)&Vs[row][c * 4] = *(const float4*)(v + goff);
        }
        __syncthreads();

        #pragma unroll
        for (int mt = 0; mt < 2; mt++) {
            float c[8][4];
            #pragma unroll
            for (int j = 0; j < 8; j++) {
                c[j][0] = 0.f; c[j][1] = 0.f; c[j][2] = 0.f; c[j][3] = 0.f;
                #pragma unroll
                for (int ks = 0; ks < 5; ks++) {
                    uint32_t b[2];
                    b[0] = __float_as_uint(Ks[j * 8 + gid][ks * 8 + tig]);
                    b[1] = __float_as_uint(Ks[j * 8 + gid][ks * 8 + tig + 4]);
                    mma_tf32(c[j], qa[mt][ks], b);
                }
            }
            float mx0 = -1e30f, mx1 = -1e30f;
            #pragma unroll
            for (int j = 0; j < 8; j++) {
                mx0 = fmaxf(mx0, fmaxf(c[j][0], c[j][1]));
                mx1 = fmaxf(mx1, fmaxf(c[j][2], c[j][3]));
            }
            mx0 = fmaxf(mx0, __shfl_xor_sync(~0u, mx0, 1));
            mx0 = fmaxf(mx0, __shfl_xor_sync(~0u, mx0, 2));
            mx1 = fmaxf(mx1, __shfl_xor_sync(~0u, mx1, 1));
            mx1 = fmaxf(mx1, __shfl_xor_sync(~0u, mx1, 2));
            float mn0 = fmaxf(mrow[mt][0], mx0);
            float mn1 = fmaxf(mrow[mt][1], mx1);
            float cor0 = __expf(mrow[mt][0] - mn0);
            float cor1 = __expf(mrow[mt][1] - mn1);
            mrow[mt][0] = mn0; mrow[mt][1] = mn1;
            float sum0 = 0.f, sum1 = 0.f;
            #pragma unroll
            for (int j = 0; j < 8; j++) {
                c[j][0] = __expf(c[j][0] - mn0);
                c[j][1] = __expf(c[j][1] - mn0);
                c[j][2] = __expf(c[j][2] - mn1);
                c[j][3] = __expf(c[j][3] - mn1);
                sum0 += c[j][0] + c[j][1];
                sum1 += c[j][2] + c[j][3];
            }
            sum0 += __shfl_xor_sync(~0u, sum0, 1);
            sum0 += __shfl_xor_sync(~0u, sum0, 2);
            sum1 += __shfl_xor_sync(~0u, sum1, 1);
            sum1 += __shfl_xor_sync(~0u, sum1, 2);
            lrow[mt][0] = lrow[mt][0] * cor0 + sum0;
            lrow[mt][1] = lrow[mt][1] * cor1 + sum1;
            #pragma unroll
            for (int n = 0; n < 5; n++) {
                o[mt][n][0] *= cor0; o[mt][n][1] *= cor0;
                o[mt][n][2] *= cor1; o[mt][n][3] *= cor1;
            }
            __syncwarp();
            #pragma unroll
            for (int j = 0; j < 8; j++) {
                *(float2*)&Ps[w][gid][j * 8 + 2 * tig]     = make_float2(c[j][0], c[j][1]);
                *(float2*)&Ps[w][gid + 8][j * 8 + 2 * tig] = make_float2(c[j][2], c[j][3]);
            }
            __syncwarp();
            #pragma unroll
            for (int kk = 0; kk < 8; kk++) {
                uint32_t pa[4];
                pa[0] = __float_as_uint(Ps[w][gid][kk * 8 + tig]);
                pa[1] = __float_as_uint(Ps[w][gid + 8][kk * 8 + tig]);
                pa[2] = __float_as_uint(Ps[w][gid][kk * 8 + tig + 4]);
                pa[3] = __float_as_uint(Ps[w][gid + 8][kk * 8 + tig + 4]);
                #pragma unroll
                for (int n = 0; n < 5; n++) {
                    uint32_t vb[2];
                    vb[0] = __float_as_uint(Vs[kk * 8 + tig][n * 8 + gid]);
                    vb[1] = __float_as_uint(Vs[kk * 8 + tig + 4][n * 8 + gid]);
                    mma_tf32(o[mt][n], pa, vb);
                }
            }
            __syncwarp();
        }
    }

    #pragma unroll
    for (int mt = 0; mt < 2; mt++) {
        float inv0 = 1.f / lrow[mt][0];
        float inv1 = 1.f / lrow[mt][1];
        int r0 = qbase + mt * 16 + gid;
        float* o0 = out + (size_t)r0 * DIM + head * DHEAD;
        float* o1 = o0 + 8 * DIM;
        #pragma unroll
        for (int n = 0; n < 5; n++) {
            *(float2*)(o0 + n * 8 + 2 * tig) = make_float2(o[mt][n][0] * inv0, o[mt][n][1] * inv0);
            *(float2*)(o1 + n * 8 + 2 * tig) = make_float2(o[mt][n][2] * inv1, o[mt][n][3] * inv1);
        }
    }
}

// ---------------- cross-attention scores (f32x2) --------------------------------
__global__ __launch_bounds__(128) void cross_scores_kernel(
    const float* __restrict__ q, const float* __restrict__ kc,
    float* __restrict__ sim)
{
    __shared__ ulonglong2 Ks[M_CTX * 10];
    int head = blockIdx.y;
    int qi = blockIdx.x * 128 + threadIdx.x;
    for (int idx = threadIdx.x; idx < M_CTX * 10; idx += 128) {
        int row = idx / 10, c = idx % 10;
        Ks[idx] = *(const ulonglong2*)(kc + (size_t)row * DIM + head * DHEAD + c * 4);
    }
    __syncthreads();
    ull q2[20];
    {
        const ulonglong2* qp = (const ulonglong2*)(q + (size_t)qi * DIM + head * DHEAD);
        ull sc = dup2(SCALE);
        #pragma unroll
        for (int i = 0; i < 10; i++) {
            ulonglong2 tq = qp[i];
            q2[2 * i]     = mul2(tq.x, sc);
            q2[2 * i + 1] = mul2(tq.y, sc);
        }
    }
    float* srow = sim + ((size_t)head * N_TOK + qi) * SIM_STRIDE;
    for (int j = 0; j < M_CTX; j++) {
        ull sa = 0ull, sb = 0ull;
        const ulonglong2* kr = &Ks[j * 10];
        #pragma unroll
        for (int i = 0; i < 10; i++) {
            ulonglong2 kv = kr[i];
            fma2(sa, q2[2 * i],     kv.x);
            fma2(sb, q2[2 * i + 1], kv.y);
        }
        srow[j] = hadd2(add2(sa, sb));
    }
}

// ---------------- FCA mask + softmax (16 rows/block) ----------------------------
__global__ __launch_bounds__(128) void fca_softmax_kernel(
    float* __restrict__ sim, const float* __restrict__ fam,
    const int* __restrict__ use_fca_p)
{
    __shared__ float fam_s[M_CTX * M_CTX];
    __shared__ float srow[16][M_CTX];
    int use_fca = *use_fca_p;
    int head = blockIdx.y;
    int qbase = blockIdx.x * 16;
    for (int i = threadIdx.x; i < M_CTX * M_CTX; i += 128)
        fam_s[i] = fam[i];
    for (int idx = threadIdx.x; idx < 16 * M_CTX; idx += 128) {
        int r = idx / M_CTX, d = idx - r * M_CTX;
        srow[r][d] = sim[((size_t)head * N_TOK + qbase + r) * SIM_STRIDE + d];
    }
    __syncthreads();
    int w = threadIdx.x >> 5, lane = threadIdx.x & 31;
    int dd[3] = { lane, lane + 32, lane + 64 };

    for (int rr = 0; rr < 4; rr++) {
        int r = w * 4 + rr;
        float* grow = sim + ((size_t)head * N_TOK + qbase + r) * SIM_STRIDE;
        if (use_fca != 0) {
            float f[3];
            float fmax_local = 0.f;
            #pragma unroll
            for (int t = 0; t < 3; t++) {
                f[t] = -1.f;
                int d = dd[t];
                if (d < M_CTX) {
                    float a = 0.f;
                    for (int kk = 0; kk < M_CTX; kk++)
                        a += srow[r][kk] * fam_s[d * M_CTX + kk];
                    f[t] = fminf(fabsf(a), 1.f);
                    fmax_local = fmaxf(fmax_local, f[t]);
                }
            }
            #pragma unroll
            for (int off = 16; off; off >>= 1)
                fmax_local = fmaxf(fmax_local, __shfl_xor_sync(~0u, fmax_local, off));
            float denom = fmax_local + 1e-6f;
            __syncwarp();
            #pragma unroll
            for (int t = 0; t < 3; t++) {
                int d = dd[t];
                if (d < M_CTX) {
                    float keep = (f[t] / denom > 0.6f) ? 0.f : -50.f;
                    srow[r][d] += keep;
                }
            }
            __syncwarp();
        }
        float mloc = -1e30f;
        #pragma unroll
        for (int t = 0; t < 3; t++)
            if (dd[t] < M_CTX) mloc = fmaxf(mloc, srow[r][dd[t]]);
        #pragma unroll
        for (int off = 16; off; off >>= 1)
            mloc = fmaxf(mloc, __shfl_xor_sync(~0u, mloc, off));
        float pv[3]; float ssum = 0.f;
        #pragma unroll
        for (int t = 0; t < 3; t++) {
            pv[t] = 0.f;
            if (dd[t] < M_CTX) { pv[t] = __expf(srow[r][dd[t]] - mloc); ssum += pv[t]; }
        }
        #pragma unroll
        for (int off = 16; off; off >>= 1)
            ssum += __shfl_xor_sync(~0u, ssum, off);
        float inv = 1.f / ssum;
        #pragma unroll
        for (int t = 0; t < 3; t++)
            if (dd[t] < M_CTX) grow[dd[t]] = pv[t] * inv;
    }
}

// ---------------- cross-attention AV (f32x2) -------------------------------------
__global__ __launch_bounds__(128) void cross_av_kernel(
    const float* __restrict__ sim, const float* __restrict__ vc,
    float* __restrict__ out)
{
    __shared__ ulonglong2 Vs[M_CTX * 10];
    int head = blockIdx.y;
    int qi = blockIdx.x * 128 + threadIdx.x;
    for (int idx = threadIdx.x; idx < M_CTX * 10; idx += 128) {
        int row = idx / 10, c = idx % 10;
        Vs[idx] = *(const ulonglong2*)(vc + (size_t)row * DIM + head * DHEAD + c * 4);
    }
    __syncthreads();
    const float* srow = sim + ((size_t)head * N_TOK + qi) * SIM_STRIDE;
    ull acc[20];
    #pragma unroll
    for (int i = 0; i < 20; i++) acc[i] = 0ull;
    for (int j = 0; j < M_CTX; j++) {
        ull pd = dup2(srow[j]);
        const ulonglong2* vr = &Vs[j * 10];
        #pragma unroll
        for (int i = 0; i < 10; i++) {
            ulonglong2 vv = vr[i];
            fma2(acc[2 * i],     pd, vv.x);
            fma2(acc[2 * i + 1], pd, vv.y);
        }
    }
    ulonglong2* op = (ulonglong2*)(out + (size_t)qi * DIM + head * DHEAD);
    #pragma unroll
    for (int i = 0; i < 10; i++) {
        ulonglong2 tv;
        tv.x = acc[2 * i];
        tv.y = acc[2 * i + 1];
        op[i] = tv;
    }
}

// ---------------- GEGLU ---------------------------------------------------------
__global__ __launch_bounds__(256) void geglu_kernel(const float* __restrict__ ff,
                                                    float* __restrict__ out) {
    int idx = blockIdx.x * 256 + threadIdx.x;
    if (idx >= N_TOK * FF_INNER) return;
    int row = idx / FF_INNER, col = idx - row * FF_INNER;
    float a = ff[(size_t)row * 2 * FF_INNER + col];
    float gt = ff[(size_t)row * 2 * FF_INNER + FF_INNER + col];
    float ge = 0.5f * gt * (1.f + erff(gt * 0.70710678118654752f));
    out[idx] = a * ge;
}

// ---------------- launch ---------------------------------------------------------
extern "C" void kernel_launch(void* const* d_in, const int* in_sizes, int n_in,
                              void* d_out, int out_size)
{
    const float* x    = (const float*)d_in[0];
    const float* ctx  = (const float*)d_in[1];
    const float* fam  = (const float*)d_in[2];
    const float* g1   = (const float*)d_in[3];
    const float* b1   = (const float*)d_in[4];
    const float* g2   = (const float*)d_in[5];
    const float* b2   = (const float*)d_in[6];
    const float* g3   = (const float*)d_in[7];
    const float* b3   = (const float*)d_in[8];
    const float* Wq1  = (const float*)d_in[9];
    const float* Wk1  = (const float*)d_in[10];
    const float* Wv1  = (const float*)d_in[11];
    const float* Wo1  = (const float*)d_in[12];
    const float* bo1  = (const float*)d_in[13];
    const float* Wq2  = (const float*)d_in[14];
    const float* Wk2  = (const float*)d_in[15];
    const float* Wv2  = (const float*)d_in[16];
    const float* Wo2  = (const float*)d_in[17];
    const float* bo2  = (const float*)d_in[18];
    const float* Wff1 = (const float*)d_in[19];
    const float* bff1 = (const float*)d_in[20];
    const float* Wff2 = (const float*)d_in[21];
    const float* bff2 = (const float*)d_in[22];
    const int*   ufca = (const int*)d_in[23];
    float* out = (float*)d_out;

    float *h, *q, *k, *v, *o, *kc, *vc, *sim, *ff, *gg;
    cudaGetSymbolAddress((void**)&h,  g_h);
    cudaGetSymbolAddress((void**)&q,  g_q);
    cudaGetSymbolAddress((void**)&k,  g_k);
    cudaGetSymbolAddress((void**)&v,  g_v);
    cudaGetSymbolAddress((void**)&o,  g_o);
    cudaGetSymbolAddress((void**)&kc, g_kc);
    cudaGetSymbolAddress((void**)&vc, g_vc);
    cudaGetSymbolAddress((void**)&sim, g_sim);
    cudaGetSymbolAddress((void**)&ff, g_ff);
    cudaGetSymbolAddress((void**)&gg, g_gg);

    dim3 g_mm(DIM / 64, N_TOK / 128, 1);
    dim3 g_qkv(DIM / 64, N_TOK / 128, 3);
    dim3 g_ctx2(DIM / 64, 1, 2);
    dim3 g_ff1(2 * FF_INNER / 64, N_TOK / 128, 1);

    // --- block 1: self-attention ---
    ln_kernel<<<N_TOK, 128>>>(x, g1, b1, h);
    tgemm_kernel<false, false><<<g_qkv, 256>>>(h, Wq1, Wk1, Wv1, nullptr, nullptr,
                                               q, k, v, N_TOK, DIM, DIM);
    self_attn_mma_kernel<<<dim3(N_TOK / 128, HEADS), 128>>>(q, k, v, o);
    tgemm_kernel<true, true><<<g_mm, 256>>>(o, Wo1, Wo1, Wo1, bo1, x,
                                            out, out, out, N_TOK, DIM, DIM);

    // --- block 2: cross-attention with FCA ---
    ln_kernel<<<N_TOK, 128>>>(out, g2, b2, h);
    tgemm_kernel<false, false><<<g_mm, 256>>>(h, Wq2, Wq2, Wq2, nullptr, nullptr,
                                              q, q, q, N_TOK, DIM, DIM);
    tgemm_kernel<false, false><<<g_ctx2, 256>>>(ctx, Wk2, Wv2, Wv2, nullptr, nullptr,
                                                kc, vc, vc, M_CTX, DIM, CTX_DIM);
    cross_scores_kernel<<<dim3(N_TOK / 128, HEADS), 128>>>(q, kc, sim);
    fca_softmax_kernel<<<dim3(N_TOK / 16, HEADS), 128>>>(sim, fam, ufca);
    cross_av_kernel<<<dim3(N_TOK / 128, HEADS), 128>>>(sim, vc, o);
    tgemm_kernel<true, true><<<g_mm, 256>>>(o, Wo2, Wo2, Wo2, bo2, out,
                                            out, out, out, N_TOK, DIM, DIM);

    // --- block 3: GEGLU feed-forward ---
    ln_kernel<<<N_TOK, 128>>>(out, g3, b3, h);
    tgemm_kernel<true, false><<<g_ff1, 256>>>(h, Wff1, Wff1, Wff1, bff1, nullptr,
                                              ff, ff, ff, N_TOK, 2 * FF_INNER, DIM);
    geglu_kernel<<<(N_TOK * FF_INNER + 255) / 256, 256>>>(ff, gg);
    tgemm_kernel<true, true><<<g_mm, 256>>>(gg, Wff2, Wff2, Wff2, bff2, out,
                                            out, out, out, N_TOK, DIM, FF_INNER);
}

// round 7
// speedup vs baseline: 2.4824x; 1.1553x over previous
#include <cuda_runtime.h>
#include <math.h>
#include <stdint.h>

#define N_TOK 4096
#define DIM 320
#define HEADS 8
#define DHEAD 40
#define CTX_DIM 768
#define M_CTX 77
#define FF_INNER 1280
#define SIM_STRIDE 80
#define SCALE 0.15811388300841898f

typedef unsigned long long ull;

// ---------------- f32x2 packed-math helpers ----------------
__device__ __forceinline__ ull dup2(float x) {
    ull r; asm("mov.b64 %0, {%1, %1};" : "=l"(r) : "f"(x)); return r;
}
__device__ __forceinline__ void fma2(ull& d, ull a, ull b) {
    asm("fma.rn.f32x2 %0, %1, %2, %0;" : "+l"(d) : "l"(a), "l"(b));
}
__device__ __forceinline__ ull mul2(ull a, ull b) {
    ull r; asm("mul.rn.f32x2 %0, %1, %2;" : "=l"(r) : "l"(a), "l"(b)); return r;
}
__device__ __forceinline__ ull add2(ull a, ull b) {
    ull r; asm("add.rn.f32x2 %0, %1, %2;" : "=l"(r) : "l"(a), "l"(b)); return r;
}
__device__ __forceinline__ float2 unpack2(ull v) {
    float2 r; asm("mov.b64 {%0, %1}, %2;" : "=f"(r.x), "=f"(r.y) : "l"(v)); return r;
}
__device__ __forceinline__ float hadd2(ull v) {
    float2 r = unpack2(v); return r.x + r.y;
}

// ---------------- tf32 m16n8k8 mma (attention) ---------------------------------
__device__ __forceinline__ void mma_tf32(float* d, const uint32_t* a, const uint32_t* b) {
    asm volatile("mma.sync.aligned.m16n8k8.row.col.f32.tf32.tf32.f32 "
        "{%0,%1,%2,%3}, {%4,%5,%6,%7}, {%8,%9}, {%0,%1,%2,%3};"
        : "+f"(d[0]), "+f"(d[1]), "+f"(d[2]), "+f"(d[3])
        : "r"(a[0]), "r"(a[1]), "r"(a[2]), "r"(a[3]), "r"(b[0]), "r"(b[1]));
}

// ---------------- bf16 m16n8k16 mma (GEMMs) -------------------------------------
__device__ __forceinline__ void mma_bf16(float* d, const uint32_t* a, const uint32_t* b) {
    asm volatile("mma.sync.aligned.m16n8k16.row.col.f32.bf16.bf16.f32 "
        "{%0,%1,%2,%3}, {%4,%5,%6,%7}, {%8,%9}, {%0,%1,%2,%3};"
        : "+f"(d[0]), "+f"(d[1]), "+f"(d[2]), "+f"(d[3])
        : "r"(a[0]), "r"(a[1]), "r"(a[2]), "r"(a[3]), "r"(b[0]), "r"(b[1]));
}

// split a pair of fp32 (consecutive k: x0=even, x1=odd) into packed bf16x2
// hi word + bf16x2 residual word. Low 16 bits hold the even-k element.
__device__ __forceinline__ void split_pack(float x0, float x1, uint32_t& h, uint32_t& l) {
    uint32_t hp;
    asm("cvt.rn.satfinite.bf16x2.f32 %0, %1, %2;" : "=r"(hp) : "f"(x1), "f"(x0));
    float f0 = __uint_as_float(hp << 16);
    float f1 = __uint_as_float(hp & 0xffff0000u);
    float r0 = x0 - f0;
    float r1 = x1 - f1;
    asm("cvt.rn.satfinite.bf16x2.f32 %0, %1, %2;" : "=r"(l) : "f"(r1), "f"(r0));
    h = hp;
}

// ---------------- scratch (device globals; no allocation allowed) ------------
__device__ float g_h[N_TOK * DIM];
__device__ float g_q[N_TOK * DIM];
__device__ float g_k[N_TOK * DIM];
__device__ float g_v[N_TOK * DIM];
__device__ float g_o[N_TOK * DIM];
__device__ float g_kc[M_CTX * DIM];
__device__ float g_vc[M_CTX * DIM];
__device__ float g_sim[HEADS * N_TOK * SIM_STRIDE];
__device__ float g_ff[N_TOK * 2 * FF_INNER];
__device__ float g_gg[N_TOK * FF_INNER];

// ---------------- LayerNorm ---------------------------------------------------
__global__ __launch_bounds__(128) void ln_kernel(const float* __restrict__ x,
                                                 const float* __restrict__ g,
                                                 const float* __restrict__ b,
                                                 float* __restrict__ out) {
    int row = blockIdx.x;
    const float* xr = x + row * DIM;
    float s = 0.f, s2 = 0.f;
    for (int i = threadIdx.x; i < DIM; i += 128) {
        float v = xr[i];
        s += v; s2 += v * v;
    }
    #pragma unroll
    for (int off = 16; off; off >>= 1) {
        s  += __shfl_xor_sync(~0u, s, off);
        s2 += __shfl_xor_sync(~0u, s2, off);
    }
    __shared__ float rs[4], rs2[4];
    int w = threadIdx.x >> 5, lane = threadIdx.x & 31;
    if (lane == 0) { rs[w] = s; rs2[w] = s2; }
    __syncthreads();
    s  = rs[0] + rs[1] + rs[2] + rs[3];
    s2 = rs2[0] + rs2[1] + rs2[2] + rs2[3];
    float mu = s * (1.f / DIM);
    float var = s2 * (1.f / DIM) - mu * mu;
    float rstd = rsqrtf(var + 1e-5f);
    float* orow = out + row * DIM;
    for (int i = threadIdx.x; i < DIM; i += 128)
        orow[i] = (xr[i] - mu) * rstd * g[i] + b[i];
}

// ---------------- bf16x3 tensor-core GEMM 128x64, warp 32x32 -------------------
// Pre-split packed bf16 operands in smem; inner loop is LDS + HMMA only.
// z-batched: blockIdx.z selects (B, C) pair.
#define AP 12   // Ah/Al pitch in uint32 (8 data + 4 pad): gid*12+tig bijective mod 32
#define BP 72   // Bh/Bl pitch in uint32: tig*8+gid bijective mod 32

template <bool BIAS, bool RES>
__global__ __launch_bounds__(256) void tgemm_kernel(
    const float* __restrict__ A,
    const float* B0, const float* B1, const float* B2,
    const float* __restrict__ bias, const float* __restrict__ res,
    float* C0, float* C1, float* C2,
    int M, int N, int K)
{
    const float* __restrict__ B = (blockIdx.z == 0) ? B0 : (blockIdx.z == 1 ? B1 : B2);
    float* __restrict__ C       = (blockIdx.z == 0) ? C0 : (blockIdx.z == 1 ? C1 : C2);

    __shared__ uint32_t Ah[2][128][AP];
    __shared__ uint32_t Al[2][128][AP];
    __shared__ uint32_t Bh[2][8][BP];
    __shared__ uint32_t Bl[2][8][BP];

    int t = threadIdx.x;
    int w = t >> 5, lane = t & 31;
    int gid = lane >> 2, tig = lane & 3;
    int wm = (w >> 1) * 32, wn = (w & 1) * 32;
    int bm = blockIdx.y * 128, bn = blockIdx.x * 64;

    // loader indices
    int a_row0 = t >> 2;            // 0..63
    int a_row1 = a_row0 + 64;       // 64..127
    int a_kq = (t & 3) * 4;         // k offset within 16-chunk
    int a_j  = (t & 3) * 2;         // packed-pair index
    int b_j  = t >> 5;              // 0..7 (k-pair row)
    int b_c  = (t & 31) * 2;        // 0..62 (col)
    int gm0 = bm + a_row0, gm1 = bm + a_row1;

    float acc[2][4][4];
    #pragma unroll
    for (int mt = 0; mt < 2; mt++)
        #pragma unroll
        for (int nt = 0; nt < 4; nt++)
            #pragma unroll
            for (int i = 0; i < 4; i++) acc[mt][nt][i] = 0.f;

    float4 aR0, aR1;
    float2 bR0, bR1;
    const float4 z4 = make_float4(0.f, 0.f, 0.f, 0.f);
    const float2 z2 = make_float2(0.f, 0.f);

    // prologue loads (chunk 0)
    aR0 = (gm0 < M) ? *(const float4*)(A + (size_t)gm0 * K + a_kq) : z4;
    aR1 = (gm1 < M) ? *(const float4*)(A + (size_t)gm1 * K + a_kq) : z4;
    bR0 = *(const float2*)(B + (size_t)(2 * b_j) * N + bn + b_c);
    bR1 = *(const float2*)(B + (size_t)(2 * b_j + 1) * N + bn + b_c);
    {
        uint32_t h0, l0, h1, l1;
        split_pack(aR0.x, aR0.y, h0, l0); split_pack(aR0.z, aR0.w, h1, l1);
        *(uint2*)&Ah[0][a_row0][a_j] = make_uint2(h0, h1);
        *(uint2*)&Al[0][a_row0][a_j] = make_uint2(l0, l1);
        split_pack(aR1.x, aR1.y, h0, l0); split_pack(aR1.z, aR1.w, h1, l1);
        *(uint2*)&Ah[0][a_row1][a_j] = make_uint2(h0, h1);
        *(uint2*)&Al[0][a_row1][a_j] = make_uint2(l0, l1);
        split_pack(bR0.x, bR1.x, h0, l0); split_pack(bR0.y, bR1.y, h1, l1);
        *(uint2*)&Bh[0][b_j][b_c] = make_uint2(h0, h1);
        *(uint2*)&Bl[0][b_j][b_c] = make_uint2(l0, l1);
    }
    __syncthreads();

    int nchunks = K >> 4;
    for (int it = 0; it < nchunks; it++) {
        int cur = it & 1;
        if (it + 1 < nchunks) {
            int k0 = (it + 1) << 4;
            aR0 = (gm0 < M) ? *(const float4*)(A + (size_t)gm0 * K + k0 + a_kq) : z4;
            aR1 = (gm1 < M) ? *(const float4*)(A + (size_t)gm1 * K + k0 + a_kq) : z4;
            bR0 = *(const float2*)(B + (size_t)(k0 + 2 * b_j) * N + bn + b_c);
            bR1 = *(const float2*)(B + (size_t)(k0 + 2 * b_j + 1) * N + bn + b_c);
        }
        // fragment loads (pure LDS, conflict-free)
        uint32_t ah[2][4], al_[2][4];
        #pragma unroll
        for (int mt = 0; mt < 2; mt++) {
            int r = wm + mt * 16 + gid;
            ah[mt][0] = Ah[cur][r][tig];       al_[mt][0] = Al[cur][r][tig];
            ah[mt][1] = Ah[cur][r + 8][tig];   al_[mt][1] = Al[cur][r + 8][tig];
            ah[mt][2] = Ah[cur][r][tig + 4];   al_[mt][2] = Al[cur][r][tig + 4];
            ah[mt][3] = Ah[cur][r + 8][tig + 4]; al_[mt][3] = Al[cur][r + 8][tig + 4];
        }
        uint32_t bh_[4][2], bl_[4][2];
        #pragma unroll
        for (int nt = 0; nt < 4; nt++) {
            int col = wn + nt * 8 + gid;
            bh_[nt][0] = Bh[cur][tig][col];     bl_[nt][0] = Bl[cur][tig][col];
            bh_[nt][1] = Bh[cur][tig + 4][col]; bl_[nt][1] = Bl[cur][tig + 4][col];
        }
        #pragma unroll
        for (int mt = 0; mt < 2; mt++)
            #pragma unroll
            for (int nt = 0; nt < 4; nt++) {
                mma_bf16(acc[mt][nt], al_[mt], bh_[nt]);
                mma_bf16(acc[mt][nt], ah[mt], bl_[nt]);
                mma_bf16(acc[mt][nt], ah[mt], bh_[nt]);
            }
        if (it + 1 < nchunks) {
            int nxt = cur ^ 1;
            uint32_t h0, l0, h1, l1;
            split_pack(aR0.x, aR0.y, h0, l0); split_pack(aR0.z, aR0.w, h1, l1);
            *(uint2*)&Ah[nxt][a_row0][a_j] = make_uint2(h0, h1);
            *(uint2*)&Al[nxt][a_row0][a_j] = make_uint2(l0, l1);
            split_pack(aR1.x, aR1.y, h0, l0); split_pack(aR1.z, aR1.w, h1, l1);
            *(uint2*)&Ah[nxt][a_row1][a_j] = make_uint2(h0, h1);
            *(uint2*)&Al[nxt][a_row1][a_j] = make_uint2(l0, l1);
            split_pack(bR0.x, bR1.x, h0, l0); split_pack(bR0.y, bR1.y, h1, l1);
            *(uint2*)&Bh[nxt][b_j][b_c] = make_uint2(h0, h1);
            *(uint2*)&Bl[nxt][b_j][b_c] = make_uint2(l0, l1);
        }
        __syncthreads();
    }

    // epilogue from c-fragments (m16n8 layout: c0,c1 row gid; c2,c3 row gid+8)
    #pragma unroll
    for (int mt = 0; mt < 2; mt++) {
        int r0 = bm + wm + mt * 16 + gid;
        int r1 = r0 + 8;
        #pragma unroll
        for (int nt = 0; nt < 4; nt++) {
            int col = bn + wn + nt * 8 + 2 * tig;
            float2 bv = make_float2(0.f, 0.f);
            if (BIAS) bv = *(const float2*)&bias[col];
            float2 lo = make_float2(acc[mt][nt][0] + bv.x, acc[mt][nt][1] + bv.y);
            float2 hi = make_float2(acc[mt][nt][2] + bv.x, acc[mt][nt][3] + bv.y);
            if (r0 < M) {
                if (RES) {
                    float2 rv = *(const float2*)(res + (size_t)r0 * N + col);
                    lo.x += rv.x; lo.y += rv.y;
                }
                *(float2*)(C + (size_t)r0 * N + col) = lo;
            }
            if (r1 < M) {
                if (RES) {
                    float2 rv = *(const float2*)(res + (size_t)r1 * N + col);
                    hi.x += rv.x; hi.y += rv.y;
                }
                *(float2*)(C + (size_t)r1 * N + col) = hi;
            }
        }
    }
}

// ---------------- self-attention: tf32 mma flash --------------------------------
__global__ __launch_bounds__(128) void self_attn_mma_kernel(
    const float* __restrict__ q, const float* __restrict__ k,
    const float* __restrict__ v, float* __restrict__ out)
{
    __shared__ float Ks[64][44];
    __shared__ float Vs[64][44];
    __shared__ float Ps[4][16][72];

    int tid = threadIdx.x;
    int w = tid >> 5, lane = tid & 31;
    int gid = lane >> 2, tig = lane & 3;
    int head = blockIdx.y;
    int qbase = blockIdx.x * 128 + w * 32;

    uint32_t qa[2][5][4];
    #pragma unroll
    for (int mt = 0; mt < 2; mt++) {
        const float* q0 = q + (size_t)(qbase + mt * 16 + gid) * DIM + head * DHEAD;
        const float* q1 = q0 + 8 * DIM;
        #pragma unroll
        for (int ks = 0; ks < 5; ks++) {
            qa[mt][ks][0] = __float_as_uint(q0[ks * 8 + tig] * SCALE);
            qa[mt][ks][1] = __float_as_uint(q1[ks * 8 + tig] * SCALE);
            qa[mt][ks][2] = __float_as_uint(q0[ks * 8 + tig + 4] * SCALE);
            qa[mt][ks][3] = __float_as_uint(q1[ks * 8 + tig + 4] * SCALE);
        }
    }

    float o[2][5][4];
    #pragma unroll
    for (int mt = 0; mt < 2; mt++)
        #pragma unroll
        for (int n = 0; n < 5; n++)
            #pragma unroll
            for (int i = 0; i < 4; i++) o[mt][n][i] = 0.f;
    float mrow[2][2], lrow[2][2];
    #pragma unroll
    for (int mt = 0; mt < 2; mt++) {
        mrow[mt][0] = -1e30f; mrow[mt][1] = -1e30f;
        lrow[mt][0] = 0.f;    lrow[mt][1] = 0.f;
    }

    for (int kt = 0; kt < N_TOK; kt += 64) {
        __syncthreads();
        #pragma unroll
        for (int it = 0; it < 5; it++) {
            int idx = tid + it * 128;
            int row = idx / 10, c = idx % 10;
            size_t goff = (size_t)(kt + row) * DIM + head * DHEAD + c * 4;
            *(float4*)&Ks[row][c * 4] = *(const float4*)(k + goff);
            *(float4*)&Vs[row][c * 4] = *(const float4*)(v + goff);
        }
        __syncthreads();

        #pragma unroll
        for (int mt = 0; mt < 2; mt++) {
            float c[8][4];
            #pragma unroll
            for (int j = 0; j < 8; j++) {
                c[j][0] = 0.f; c[j][1] = 0.f; c[j][2] = 0.f; c[j][3] = 0.f;
                #pragma unroll
                for (int ks = 0; ks < 5; ks++) {
                    uint32_t b[2];
                    b[0] = __float_as_uint(Ks[j * 8 + gid][ks * 8 + tig]);
                    b[1] = __float_as_uint(Ks[j * 8 + gid][ks * 8 + tig + 4]);
                    mma_tf32(c[j], qa[mt][ks], b);
                }
            }
            float mx0 = -1e30f, mx1 = -1e30f;
            #pragma unroll
            for (int j = 0; j < 8; j++) {
                mx0 = fmaxf(mx0, fmaxf(c[j][0], c[j][1]));
                mx1 = fmaxf(mx1, fmaxf(c[j][2], c[j][3]));
            }
            mx0 = fmaxf(mx0, __shfl_xor_sync(~0u, mx0, 1));
            mx0 = fmaxf(mx0, __shfl_xor_sync(~0u, mx0, 2));
            mx1 = fmaxf(mx1, __shfl_xor_sync(~0u, mx1, 1));
            mx1 = fmaxf(mx1, __shfl_xor_sync(~0u, mx1, 2));
            float mn0 = fmaxf(mrow[mt][0], mx0);
            float mn1 = fmaxf(mrow[mt][1], mx1);
            float cor0 = __expf(mrow[mt][0] - mn0);
            float cor1 = __expf(mrow[mt][1] - mn1);
            mrow[mt][0] = mn0; mrow[mt][1] = mn1;
            float sum0 = 0.f, sum1 = 0.f;
            #pragma unroll
            for (int j = 0; j < 8; j++) {
                c[j][0] = __expf(c[j][0] - mn0);
                c[j][1] = __expf(c[j][1] - mn0);
                c[j][2] = __expf(c[j][2] - mn1);
                c[j][3] = __expf(c[j][3] - mn1);
                sum0 += c[j][0] + c[j][1];
                sum1 += c[j][2] + c[j][3];
            }
            sum0 += __shfl_xor_sync(~0u, sum0, 1);
            sum0 += __shfl_xor_sync(~0u, sum0, 2);
            sum1 += __shfl_xor_sync(~0u, sum1, 1);
            sum1 += __shfl_xor_sync(~0u, sum1, 2);
            lrow[mt][0] = lrow[mt][0] * cor0 + sum0;
            lrow[mt][1] = lrow[mt][1] * cor1 + sum1;
            #pragma unroll
            for (int n = 0; n < 5; n++) {
                o[mt][n][0] *= cor0; o[mt][n][1] *= cor0;
                o[mt][n][2] *= cor1; o[mt][n][3] *= cor1;
            }
            __syncwarp();
            #pragma unroll
            for (int j = 0; j < 8; j++) {
                *(float2*)&Ps[w][gid][j * 8 + 2 * tig]     = make_float2(c[j][0], c[j][1]);
                *(float2*)&Ps[w][gid + 8][j * 8 + 2 * tig] = make_float2(c[j][2], c[j][3]);
            }
            __syncwarp();
            #pragma unroll
            for (int kk = 0; kk < 8; kk++) {
                uint32_t pa[4];
                pa[0] = __float_as_uint(Ps[w][gid][kk * 8 + tig]);
                pa[1] = __float_as_uint(Ps[w][gid + 8][kk * 8 + tig]);
                pa[2] = __float_as_uint(Ps[w][gid][kk * 8 + tig + 4]);
                pa[3] = __float_as_uint(Ps[w][gid + 8][kk * 8 + tig + 4]);
                #pragma unroll
                for (int n = 0; n < 5; n++) {
                    uint32_t vb[2];
                    vb[0] = __float_as_uint(Vs[kk * 8 + tig][n * 8 + gid]);
                    vb[1] = __float_as_uint(Vs[kk * 8 + tig + 4][n * 8 + gid]);
                    mma_tf32(o[mt][n], pa, vb);
                }
            }
            __syncwarp();
        }
    }

    #pragma unroll
    for (int mt = 0; mt < 2; mt++) {
        float inv0 = 1.f / lrow[mt][0];
        float inv1 = 1.f / lrow[mt][1];
        int r0 = qbase + mt * 16 + gid;
        float* o0 = out + (size_t)r0 * DIM + head * DHEAD;
        float* o1 = o0 + 8 * DIM;
        #pragma unroll
        for (int n = 0; n < 5; n++) {
            *(float2*)(o0 + n * 8 + 2 * tig) = make_float2(o[mt][n][0] * inv0, o[mt][n][1] * inv0);
            *(float2*)(o1 + n * 8 + 2 * tig) = make_float2(o[mt][n][2] * inv1, o[mt][n][3] * inv1);
        }
    }
}

// ---------------- cross-attention scores (f32x2) --------------------------------
__global__ __launch_bounds__(128) void cross_scores_kernel(
    const float* __restrict__ q, const float* __restrict__ kc,
    float* __restrict__ sim)
{
    __shared__ ulonglong2 Ks[M_CTX * 10];
    int head = blockIdx.y;
    int qi = blockIdx.x * 128 + threadIdx.x;
    for (int idx = threadIdx.x; idx < M_CTX * 10; idx += 128) {
        int row = idx / 10, c = idx % 10;
        Ks[idx] = *(const ulonglong2*)(kc + (size_t)row * DIM + head * DHEAD + c * 4);
    }
    __syncthreads();
    ull q2[20];
    {
        const ulonglong2* qp = (const ulonglong2*)(q + (size_t)qi * DIM + head * DHEAD);
        ull sc = dup2(SCALE);
        #pragma unroll
        for (int i = 0; i < 10; i++) {
            ulonglong2 tq = qp[i];
            q2[2 * i]     = mul2(tq.x, sc);
            q2[2 * i + 1] = mul2(tq.y, sc);
        }
    }
    float* srow = sim + ((size_t)head * N_TOK + qi) * SIM_STRIDE;
    for (int j = 0; j < M_CTX; j++) {
        ull sa = 0ull, sb = 0ull;
        const ulonglong2* kr = &Ks[j * 10];
        #pragma unroll
        for (int i = 0; i < 10; i++) {
            ulonglong2 kv = kr[i];
            fma2(sa, q2[2 * i],     kv.x);
            fma2(sb, q2[2 * i + 1], kv.y);
        }
        srow[j] = hadd2(add2(sa, sb));
    }
}

// ---------------- FCA mask + softmax (16 rows/block) ----------------------------
__global__ __launch_bounds__(128) void fca_softmax_kernel(
    float* __restrict__ sim, const float* __restrict__ fam,
    const int* __restrict__ use_fca_p)
{
    __shared__ float fam_s[M_CTX * M_CTX];
    __shared__ float srow[16][M_CTX];
    int use_fca = *use_fca_p;
    int head = blockIdx.y;
    int qbase = blockIdx.x * 16;
    for (int i = threadIdx.x; i < M_CTX * M_CTX; i += 128)
        fam_s[i] = fam[i];
    for (int idx = threadIdx.x; idx < 16 * M_CTX; idx += 128) {
        int r = idx / M_CTX, d = idx - r * M_CTX;
        srow[r][d] = sim[((size_t)head * N_TOK + qbase + r) * SIM_STRIDE + d];
    }
    __syncthreads();
    int w = threadIdx.x >> 5, lane = threadIdx.x & 31;
    int dd[3] = { lane, lane + 32, lane + 64 };

    for (int rr = 0; rr < 4; rr++) {
        int r = w * 4 + rr;
        float* grow = sim + ((size_t)head * N_TOK + qbase + r) * SIM_STRIDE;
        if (use_fca != 0) {
            float f[3];
            float fmax_local = 0.f;
            #pragma unroll
            for (int t = 0; t < 3; t++) {
                f[t] = -1.f;
                int d = dd[t];
                if (d < M_CTX) {
                    float a = 0.f;
                    for (int kk = 0; kk < M_CTX; kk++)
                        a += srow[r][kk] * fam_s[d * M_CTX + kk];
                    f[t] = fminf(fabsf(a), 1.f);
                    fmax_local = fmaxf(fmax_local, f[t]);
                }
            }
            #pragma unroll
            for (int off = 16; off; off >>= 1)
                fmax_local = fmaxf(fmax_local, __shfl_xor_sync(~0u, fmax_local, off));
            float denom = fmax_local + 1e-6f;
            __syncwarp();
            #pragma unroll
            for (int t = 0; t < 3; t++) {
                int d = dd[t];
                if (d < M_CTX) {
                    float keep = (f[t] / denom > 0.6f) ? 0.f : -50.f;
                    srow[r][d] += keep;
                }
            }
            __syncwarp();
        }
        float mloc = -1e30f;
        #pragma unroll
        for (int t = 0; t < 3; t++)
            if (dd[t] < M_CTX) mloc = fmaxf(mloc, srow[r][dd[t]]);
        #pragma unroll
        for (int off = 16; off; off >>= 1)
            mloc = fmaxf(mloc, __shfl_xor_sync(~0u, mloc, off));
        float pv[3]; float ssum = 0.f;
        #pragma unroll
        for (int t = 0; t < 3; t++) {
            pv[t] = 0.f;
            if (dd[t] < M_CTX) { pv[t] = __expf(srow[r][dd[t]] - mloc); ssum += pv[t]; }
        }
        #pragma unroll
        for (int off = 16; off; off >>= 1)
            ssum += __shfl_xor_sync(~0u, ssum, off);
        float inv = 1.f / ssum;
        #pragma unroll
        for (int t = 0; t < 3; t++)
            if (dd[t] < M_CTX) grow[dd[t]] = pv[t] * inv;
    }
}

// ---------------- cross-attention AV (f32x2) -------------------------------------
__global__ __launch_bounds__(128) void cross_av_kernel(
    const float* __restrict__ sim, const float* __restrict__ vc,
    float* __restrict__ out)
{
    __shared__ ulonglong2 Vs[M_CTX * 10];
    int head = blockIdx.y;
    int qi = blockIdx.x * 128 + threadIdx.x;
    for (int idx = threadIdx.x; idx < M_CTX * 10; idx += 128) {
        int row = idx / 10, c = idx % 10;
        Vs[idx] = *(const ulonglong2*)(vc + (size_t)row * DIM + head * DHEAD + c * 4);
    }
    __syncthreads();
    const float* srow = sim + ((size_t)head * N_TOK + qi) * SIM_STRIDE;
    ull acc[20];
    #pragma unroll
    for (int i = 0; i < 20; i++) acc[i] = 0ull;
    for (int j = 0; j < M_CTX; j++) {
        ull pd = dup2(srow[j]);
        const ulonglong2* vr = &Vs[j * 10];
        #pragma unroll
        for (int i = 0; i < 10; i++) {
            ulonglong2 vv = vr[i];
            fma2(acc[2 * i],     pd, vv.x);
            fma2(acc[2 * i + 1], pd, vv.y);
        }
    }
    ulonglong2* op = (ulonglong2*)(out + (size_t)qi * DIM + head * DHEAD);
    #pragma unroll
    for (int i = 0; i < 10; i++) {
        ulonglong2 tv;
        tv.x = acc[2 * i];
        tv.y = acc[2 * i + 1];
        op[i] = tv;
    }
}

// ---------------- GEGLU ---------------------------------------------------------
__global__ __launch_bounds__(256) void geglu_kernel(const float* __restrict__ ff,
                                                    float* __restrict__ out) {
    int idx = blockIdx.x * 256 + threadIdx.x;
    if (idx >= N_TOK * FF_INNER) return;
    int row = idx / FF_INNER, col = idx - row * FF_INNER;
    float a = ff[(size_t)row * 2 * FF_INNER + col];
    float gt = ff[(size_t)row * 2 * FF_INNER + FF_INNER + col];
    float ge = 0.5f * gt * (1.f + erff(gt * 0.70710678118654752f));
    out[idx] = a * ge;
}

// ---------------- launch ---------------------------------------------------------
extern "C" void kernel_launch(void* const* d_in, const int* in_sizes, int n_in,
                              void* d_out, int out_size)
{
    const float* x    = (const float*)d_in[0];
    const float* ctx  = (const float*)d_in[1];
    const float* fam  = (const float*)d_in[2];
    const float* g1   = (const float*)d_in[3];
    const float* b1   = (const float*)d_in[4];
    const float* g2   = (const float*)d_in[5];
    const float* b2   = (const float*)d_in[6];
    const float* g3   = (const float*)d_in[7];
    const float* b3   = (const float*)d_in[8];
    const float* Wq1  = (const float*)d_in[9];
    const float* Wk1  = (const float*)d_in[10];
    const float* Wv1  = (const float*)d_in[11];
    const float* Wo1  = (const float*)d_in[12];
    const float* bo1  = (const float*)d_in[13];
    const float* Wq2  = (const float*)d_in[14];
    const float* Wk2  = (const float*)d_in[15];
    const float* Wv2  = (const float*)d_in[16];
    const float* Wo2  = (const float*)d_in[17];
    const float* bo2  = (const float*)d_in[18];
    const float* Wff1 = (const float*)d_in[19];
    const float* bff1 = (const float*)d_in[20];
    const float* Wff2 = (const float*)d_in[21];
    const float* bff2 = (const float*)d_in[22];
    const int*   ufca = (const int*)d_in[23];
    float* out = (float*)d_out;

    float *h, *q, *k, *v, *o, *kc, *vc, *sim, *ff, *gg;
    cudaGetSymbolAddress((void**)&h,  g_h);
    cudaGetSymbolAddress((void**)&q,  g_q);
    cudaGetSymbolAddress((void**)&k,  g_k);
    cudaGetSymbolAddress((void**)&v,  g_v);
    cudaGetSymbolAddress((void**)&o,  g_o);
    cudaGetSymbolAddress((void**)&kc, g_kc);
    cudaGetSymbolAddress((void**)&vc, g_vc);
    cudaGetSymbolAddress((void**)&sim, g_sim);
    cudaGetSymbolAddress((void**)&ff, g_ff);
    cudaGetSymbolAddress((void**)&gg, g_gg);

    dim3 g_mm(DIM / 64, N_TOK / 128, 1);
    dim3 g_qkv(DIM / 64, N_TOK / 128, 3);
    dim3 g_ctx2(DIM / 64, 1, 2);
    dim3 g_ff1(2 * FF_INNER / 64, N_TOK / 128, 1);

    // --- block 1: self-attention ---
    ln_kernel<<<N_TOK, 128>>>(x, g1, b1, h);
    tgemm_kernel<false, false><<<g_qkv, 256>>>(h, Wq1, Wk1, Wv1, nullptr, nullptr,
                                               q, k, v, N_TOK, DIM, DIM);
    self_attn_mma_kernel<<<dim3(N_TOK / 128, HEADS), 128>>>(q, k, v, o);
    tgemm_kernel<true, true><<<g_mm, 256>>>(o, Wo1, Wo1, Wo1, bo1, x,
                                            out, out, out, N_TOK, DIM, DIM);

    // --- block 2: cross-attention with FCA ---
    ln_kernel<<<N_TOK, 128>>>(out, g2, b2, h);
    tgemm_kernel<false, false><<<g_mm, 256>>>(h, Wq2, Wq2, Wq2, nullptr, nullptr,
                                              q, q, q, N_TOK, DIM, DIM);
    tgemm_kernel<false, false><<<g_ctx2, 256>>>(ctx, Wk2, Wv2, Wv2, nullptr, nullptr,
                                                kc, vc, vc, M_CTX, DIM, CTX_DIM);
    cross_scores_kernel<<<dim3(N_TOK / 128, HEADS), 128>>>(q, kc, sim);
    fca_softmax_kernel<<<dim3(N_TOK / 16, HEADS), 128>>>(sim, fam, ufca);
    cross_av_kernel<<<dim3(N_TOK / 128, HEADS), 128>>>(sim, vc, o);
    tgemm_kernel<true, true><<<g_mm, 256>>>(o, Wo2, Wo2, Wo2, bo2, out,
                                            out, out, out, N_TOK, DIM, DIM);

    // --- block 3: GEGLU feed-forward ---
    ln_kernel<<<N_TOK, 128>>>(out, g3, b3, h);
    tgemm_kernel<true, false><<<g_ff1, 256>>>(h, Wff1, Wff1, Wff1, bff1, nullptr,
                                              ff, ff, ff, N_TOK, 2 * FF_INNER, DIM);
    geglu_kernel<<<(N_TOK * FF_INNER + 255) / 256, 256>>>(ff, gg);
    tgemm_kernel<true, true><<<g_mm, 256>>>(gg, Wff2, Wff2, Wff2, bff2, out,
                                            out, out, out, N_TOK, DIM, FF_INNER);
}

// round 8
// speedup vs baseline: 2.6033x; 1.0487x over previous
#include <cuda_runtime.h>
#include <math.h>
#include <stdint.h>

#define N_TOK 4096
#define DIM 320
#define HEADS 8
#define DHEAD 40
#define CTX_DIM 768
#define M_CTX 77
#define FF_INNER 1280
#define SIM_STRIDE 80
#define SCALE 0.15811388300841898f

typedef unsigned long long ull;

// ---------------- f32x2 packed-math helpers ----------------
__device__ __forceinline__ ull dup2(float x) {
    ull r; asm("mov.b64 %0, {%1, %1};" : "=l"(r) : "f"(x)); return r;
}
__device__ __forceinline__ void fma2(ull& d, ull a, ull b) {
    asm("fma.rn.f32x2 %0, %1, %2, %0;" : "+l"(d) : "l"(a), "l"(b));
}
__device__ __forceinline__ ull mul2(ull a, ull b) {
    ull r; asm("mul.rn.f32x2 %0, %1, %2;" : "=l"(r) : "l"(a), "l"(b)); return r;
}
__device__ __forceinline__ ull add2(ull a, ull b) {
    ull r; asm("add.rn.f32x2 %0, %1, %2;" : "=l"(r) : "l"(a), "l"(b)); return r;
}
__device__ __forceinline__ float2 unpack2(ull v) {
    float2 r; asm("mov.b64 {%0, %1}, %2;" : "=f"(r.x), "=f"(r.y) : "l"(v)); return r;
}
__device__ __forceinline__ float hadd2(ull v) {
    float2 r = unpack2(v); return r.x + r.y;
}

// ---------------- tf32 m16n8k8 mma (attention) ---------------------------------
__device__ __forceinline__ void mma_tf32(float* d, const uint32_t* a, const uint32_t* b) {
    asm volatile("mma.sync.aligned.m16n8k8.row.col.f32.tf32.tf32.f32 "
        "{%0,%1,%2,%3}, {%4,%5,%6,%7}, {%8,%9}, {%0,%1,%2,%3};"
        : "+f"(d[0]), "+f"(d[1]), "+f"(d[2]), "+f"(d[3])
        : "r"(a[0]), "r"(a[1]), "r"(a[2]), "r"(a[3]), "r"(b[0]), "r"(b[1]));
}

// ---------------- bf16 m16n8k16 mma (GEMMs) -------------------------------------
__device__ __forceinline__ void mma_bf16(float* d, const uint32_t* a, const uint32_t* b) {
    asm volatile("mma.sync.aligned.m16n8k16.row.col.f32.bf16.bf16.f32 "
        "{%0,%1,%2,%3}, {%4,%5,%6,%7}, {%8,%9}, {%0,%1,%2,%3};"
        : "+f"(d[0]), "+f"(d[1]), "+f"(d[2]), "+f"(d[3])
        : "r"(a[0]), "r"(a[1]), "r"(a[2]), "r"(a[3]), "r"(b[0]), "r"(b[1]));
}

// split a pair of fp32 (consecutive k: x0=even, x1=odd) into packed bf16x2
// hi word + bf16x2 residual word. Low 16 bits hold the even-k element.
__device__ __forceinline__ void split_pack(float x0, float x1, uint32_t& h, uint32_t& l) {
    uint32_t hp;
    asm("cvt.rn.satfinite.bf16x2.f32 %0, %1, %2;" : "=r"(hp) : "f"(x1), "f"(x0));
    float f0 = __uint_as_float(hp << 16);
    float f1 = __uint_as_float(hp & 0xffff0000u);
    float r0 = x0 - f0;
    float r1 = x1 - f1;
    asm("cvt.rn.satfinite.bf16x2.f32 %0, %1, %2;" : "=r"(l) : "f"(r1), "f"(r0));
    h = hp;
}

// ---------------- scratch (device globals; no allocation allowed) ------------
__device__ float g_h[N_TOK * DIM];
__device__ float g_q[N_TOK * DIM];
__device__ float g_k[N_TOK * DIM];
__device__ float g_v[N_TOK * DIM];
__device__ float g_o[N_TOK * DIM];
__device__ float g_kc[M_CTX * DIM];
__device__ float g_vc[M_CTX * DIM];
__device__ float g_sim[HEADS * N_TOK * SIM_STRIDE];
__device__ float g_ff[N_TOK * 2 * FF_INNER];
__device__ float g_gg[N_TOK * FF_INNER];

// ---------------- LayerNorm ---------------------------------------------------
__global__ __launch_bounds__(128) void ln_kernel(const float* __restrict__ x,
                                                 const float* __restrict__ g,
                                                 const float* __restrict__ b,
                                                 float* __restrict__ out) {
    int row = blockIdx.x;
    const float* xr = x + row * DIM;
    float s = 0.f, s2 = 0.f;
    for (int i = threadIdx.x; i < DIM; i += 128) {
        float v = xr[i];
        s += v; s2 += v * v;
    }
    #pragma unroll
    for (int off = 16; off; off >>= 1) {
        s  += __shfl_xor_sync(~0u, s, off);
        s2 += __shfl_xor_sync(~0u, s2, off);
    }
    __shared__ float rs[4], rs2[4];
    int w = threadIdx.x >> 5, lane = threadIdx.x & 31;
    if (lane == 0) { rs[w] = s; rs2[w] = s2; }
    __syncthreads();
    s  = rs[0] + rs[1] + rs[2] + rs[3];
    s2 = rs2[0] + rs2[1] + rs2[2] + rs2[3];
    float mu = s * (1.f / DIM);
    float var = s2 * (1.f / DIM) - mu * mu;
    float rstd = rsqrtf(var + 1e-5f);
    float* orow = out + row * DIM;
    for (int i = threadIdx.x; i < DIM; i += 128)
        orow[i] = (xr[i] - mu) * rstd * g[i] + b[i];
}

// ---------------- bf16x3 tensor-core GEMM 64x64, warp 16x32 --------------------
// Pre-split packed bf16 operands in smem; inner loop is LDS + HMMA only.
// z-batched: blockIdx.z selects (B, C) pair.
#define AP 12   // Ah/Al pitch in uint32: (12*row + j) bank-bijective for frag pattern
#define BP 72   // Bh/Bl pitch in uint32: (72*j + col) bank-bijective for frag pattern

template <bool BIAS, bool RES>
__global__ __launch_bounds__(256) void tgemm_kernel(
    const float* __restrict__ A,
    const float* B0, const float* B1, const float* B2,
    const float* __restrict__ bias, const float* __restrict__ res,
    float* C0, float* C1, float* C2,
    int M, int N, int K)
{
    const float* __restrict__ B = (blockIdx.z == 0) ? B0 : (blockIdx.z == 1 ? B1 : B2);
    float* __restrict__ C       = (blockIdx.z == 0) ? C0 : (blockIdx.z == 1 ? C1 : C2);

    __shared__ uint32_t Ah[2][64][AP];
    __shared__ uint32_t Al[2][64][AP];
    __shared__ uint32_t Bh[2][8][BP];
    __shared__ uint32_t Bl[2][8][BP];

    int t = threadIdx.x;
    int w = t >> 5, lane = t & 31;
    int gid = lane >> 2, tig = lane & 3;
    int wm = (w >> 1) * 16, wn = (w & 1) * 32;   // 4x2 warp grid over 64x64
    int bm = blockIdx.y * 64, bn = blockIdx.x * 64;

    // loader indices
    int a_row = t >> 2;             // 0..63
    int a_kq = (t & 3) * 4;         // k offset within 16-chunk
    int a_j  = (t & 3) * 2;         // packed-pair index
    int b_j  = t >> 5;              // 0..7 (k-pair row)
    int b_c  = (t & 31) * 2;        // 0..62 (col)
    int gm = bm + a_row;

    float acc[4][4];
    #pragma unroll
    for (int nt = 0; nt < 4; nt++)
        #pragma unroll
        for (int i = 0; i < 4; i++) acc[nt][i] = 0.f;

    float4 aR;
    float2 bR0, bR1;
    const float4 z4 = make_float4(0.f, 0.f, 0.f, 0.f);

    // prologue loads (chunk 0)
    aR = (gm < M) ? *(const float4*)(A + (size_t)gm * K + a_kq) : z4;
    bR0 = *(const float2*)(B + (size_t)(2 * b_j) * N + bn + b_c);
    bR1 = *(const float2*)(B + (size_t)(2 * b_j + 1) * N + bn + b_c);
    {
        uint32_t h0, l0, h1, l1;
        split_pack(aR.x, aR.y, h0, l0); split_pack(aR.z, aR.w, h1, l1);
        *(uint2*)&Ah[0][a_row][a_j] = make_uint2(h0, h1);
        *(uint2*)&Al[0][a_row][a_j] = make_uint2(l0, l1);
        split_pack(bR0.x, bR1.x, h0, l0); split_pack(bR0.y, bR1.y, h1, l1);
        *(uint2*)&Bh[0][b_j][b_c] = make_uint2(h0, h1);
        *(uint2*)&Bl[0][b_j][b_c] = make_uint2(l0, l1);
    }
    __syncthreads();

    int nchunks = K >> 4;
    for (int it = 0; it < nchunks; it++) {
        int cur = it & 1;
        if (it + 1 < nchunks) {
            int k0 = (it + 1) << 4;
            aR = (gm < M) ? *(const float4*)(A + (size_t)gm * K + k0 + a_kq) : z4;
            bR0 = *(const float2*)(B + (size_t)(k0 + 2 * b_j) * N + bn + b_c);
            bR1 = *(const float2*)(B + (size_t)(k0 + 2 * b_j + 1) * N + bn + b_c);
        }
        // fragment loads (pure LDS, conflict-free)
        uint32_t ah[4], al_[4];
        {
            int r = wm + gid;
            ah[0] = Ah[cur][r][tig];         al_[0] = Al[cur][r][tig];
            ah[1] = Ah[cur][r + 8][tig];     al_[1] = Al[cur][r + 8][tig];
            ah[2] = Ah[cur][r][tig + 4];     al_[2] = Al[cur][r][tig + 4];
            ah[3] = Ah[cur][r + 8][tig + 4]; al_[3] = Al[cur][r + 8][tig + 4];
        }
        uint32_t bh_[4][2], bl_[4][2];
        #pragma unroll
        for (int nt = 0; nt < 4; nt++) {
            int col = wn + nt * 8 + gid;
            bh_[nt][0] = Bh[cur][tig][col];     bl_[nt][0] = Bl[cur][tig][col];
            bh_[nt][1] = Bh[cur][tig + 4][col]; bl_[nt][1] = Bl[cur][tig + 4][col];
        }
        #pragma unroll
        for (int nt = 0; nt < 4; nt++) {
            mma_bf16(acc[nt], al_, bh_[nt]);
            mma_bf16(acc[nt], ah, bl_[nt]);
            mma_bf16(acc[nt], ah, bh_[nt]);
        }
        if (it + 1 < nchunks) {
            int nxt = cur ^ 1;
            uint32_t h0, l0, h1, l1;
            split_pack(aR.x, aR.y, h0, l0); split_pack(aR.z, aR.w, h1, l1);
            *(uint2*)&Ah[nxt][a_row][a_j] = make_uint2(h0, h1);
            *(uint2*)&Al[nxt][a_row][a_j] = make_uint2(l0, l1);
            split_pack(bR0.x, bR1.x, h0, l0); split_pack(bR0.y, bR1.y, h1, l1);
            *(uint2*)&Bh[nxt][b_j][b_c] = make_uint2(h0, h1);
            *(uint2*)&Bl[nxt][b_j][b_c] = make_uint2(l0, l1);
        }
        __syncthreads();
    }

    // epilogue from c-fragments (m16n8 layout: c0,c1 row gid; c2,c3 row gid+8)
    {
        int r0 = bm + wm + gid;
        int r1 = r0 + 8;
        #pragma unroll
        for (int nt = 0; nt < 4; nt++) {
            int col = bn + wn + nt * 8 + 2 * tig;
            float2 bv = make_float2(0.f, 0.f);
            if (BIAS) bv = *(const float2*)&bias[col];
            float2 lo = make_float2(acc[nt][0] + bv.x, acc[nt][1] + bv.y);
            float2 hi = make_float2(acc[nt][2] + bv.x, acc[nt][3] + bv.y);
            if (r0 < M) {
                if (RES) {
                    float2 rv = *(const float2*)(res + (size_t)r0 * N + col);
                    lo.x += rv.x; lo.y += rv.y;
                }
                *(float2*)(C + (size_t)r0 * N + col) = lo;
            }
            if (r1 < M) {
                if (RES) {
                    float2 rv = *(const float2*)(res + (size_t)r1 * N + col);
                    hi.x += rv.x; hi.y += rv.y;
                }
                *(float2*)(C + (size_t)r1 * N + col) = hi;
            }
        }
    }
}

// ---------------- self-attention: tf32 mma flash --------------------------------
__global__ __launch_bounds__(128) void self_attn_mma_kernel(
    const float* __restrict__ q, const float* __restrict__ k,
    const float* __restrict__ v, float* __restrict__ out)
{
    __shared__ float Ks[64][44];
    __shared__ float Vs[64][44];
    __shared__ float Ps[4][16][72];

    int tid = threadIdx.x;
    int w = tid >> 5, lane = tid & 31;
    int gid = lane >> 2, tig = lane & 3;
    int head = blockIdx.y;
    int qbase = blockIdx.x * 128 + w * 32;

    uint32_t qa[2][5][4];
    #pragma unroll
    for (int mt = 0; mt < 2; mt++) {
        const float* q0 = q + (size_t)(qbase + mt * 16 + gid) * DIM + head * DHEAD;
        const float* q1 = q0 + 8 * DIM;
        #pragma unroll
        for (int ks = 0; ks < 5; ks++) {
            qa[mt][ks][0] = __float_as_uint(q0[ks * 8 + tig] * SCALE);
            qa[mt][ks][1] = __float_as_uint(q1[ks * 8 + tig] * SCALE);
            qa[mt][ks][2] = __float_as_uint(q0[ks * 8 + tig + 4] * SCALE);
            qa[mt][ks][3] = __float_as_uint(q1[ks * 8 + tig + 4] * SCALE);
        }
    }

    float o[2][5][4];
    #pragma unroll
    for (int mt = 0; mt < 2; mt++)
        #pragma unroll
        for (int n = 0; n < 5; n++)
            #pragma unroll
            for (int i = 0; i < 4; i++) o[mt][n][i] = 0.f;
    float mrow[2][2], lrow[2][2];
    #pragma unroll
    for (int mt = 0; mt < 2; mt++) {
        mrow[mt][0] = -1e30f; mrow[mt][1] = -1e30f;
        lrow[mt][0] = 0.f;    lrow[mt][1] = 0.f;
    }

    for (int kt = 0; kt < N_TOK; kt += 64) {
        __syncthreads();
        #pragma unroll
        for (int it = 0; it < 5; it++) {
            int idx = tid + it * 128;
            int row = idx / 10, c = idx % 10;
            size_t goff = (size_t)(kt + row) * DIM + head * DHEAD + c * 4;
            *(float4*)&Ks[row][c * 4] = *(const float4*)(k + goff);
            *(float4*)&Vs[row][c * 4] = *(const float4*)(v + goff);
        }
        __syncthreads();

        #pragma unroll
        for (int mt = 0; mt < 2; mt++) {
            float c[8][4];
            #pragma unroll
            for (int j = 0; j < 8; j++) {
                c[j][0] = 0.f; c[j][1] = 0.f; c[j][2] = 0.f; c[j][3] = 0.f;
                #pragma unroll
                for (int ks = 0; ks < 5; ks++) {
                    uint32_t b[2];
                    b[0] = __float_as_uint(Ks[j * 8 + gid][ks * 8 + tig]);
                    b[1] = __float_as_uint(Ks[j * 8 + gid][ks * 8 + tig + 4]);
                    mma_tf32(c[j], qa[mt][ks], b);
                }
            }
            float mx0 = -1e30f, mx1 = -1e30f;
            #pragma unroll
            for (int j = 0; j < 8; j++) {
                mx0 = fmaxf(mx0, fmaxf(c[j][0], c[j][1]));
                mx1 = fmaxf(mx1, fmaxf(c[j][2], c[j][3]));
            }
            mx0 = fmaxf(mx0, __shfl_xor_sync(~0u, mx0, 1));
            mx0 = fmaxf(mx0, __shfl_xor_sync(~0u, mx0, 2));
            mx1 = fmaxf(mx1, __shfl_xor_sync(~0u, mx1, 1));
            mx1 = fmaxf(mx1, __shfl_xor_sync(~0u, mx1, 2));
            float mn0 = fmaxf(mrow[mt][0], mx0);
            float mn1 = fmaxf(mrow[mt][1], mx1);
            float cor0 = __expf(mrow[mt][0] - mn0);
            float cor1 = __expf(mrow[mt][1] - mn1);
            mrow[mt][0] = mn0; mrow[mt][1] = mn1;
            float sum0 = 0.f, sum1 = 0.f;
            #pragma unroll
            for (int j = 0; j < 8; j++) {
                c[j][0] = __expf(c[j][0] - mn0);
                c[j][1] = __expf(c[j][1] - mn0);
                c[j][2] = __expf(c[j][2] - mn1);
                c[j][3] = __expf(c[j][3] - mn1);
                sum0 += c[j][0] + c[j][1];
                sum1 += c[j][2] + c[j][3];
            }
            sum0 += __shfl_xor_sync(~0u, sum0, 1);
            sum0 += __shfl_xor_sync(~0u, sum0, 2);
            sum1 += __shfl_xor_sync(~0u, sum1, 1);
            sum1 += __shfl_xor_sync(~0u, sum1, 2);
            lrow[mt][0] = lrow[mt][0] * cor0 + sum0;
            lrow[mt][1] = lrow[mt][1] * cor1 + sum1;
            #pragma unroll
            for (int n = 0; n < 5; n++) {
                o[mt][n][0] *= cor0; o[mt][n][1] *= cor0;
                o[mt][n][2] *= cor1; o[mt][n][3] *= cor1;
            }
            __syncwarp();
            #pragma unroll
            for (int j = 0; j < 8; j++) {
                *(float2*)&Ps[w][gid][j * 8 + 2 * tig]     = make_float2(c[j][0], c[j][1]);
                *(float2*)&Ps[w][gid + 8][j * 8 + 2 * tig] = make_float2(c[j][2], c[j][3]);
            }
            __syncwarp();
            #pragma unroll
            for (int kk = 0; kk < 8; kk++) {
                uint32_t pa[4];
                pa[0] = __float_as_uint(Ps[w][gid][kk * 8 + tig]);
                pa[1] = __float_as_uint(Ps[w][gid + 8][kk * 8 + tig]);
                pa[2] = __float_as_uint(Ps[w][gid][kk * 8 + tig + 4]);
                pa[3] = __float_as_uint(Ps[w][gid + 8][kk * 8 + tig + 4]);
                #pragma unroll
                for (int n = 0; n < 5; n++) {
                    uint32_t vb[2];
                    vb[0] = __float_as_uint(Vs[kk * 8 + tig][n * 8 + gid]);
                    vb[1] = __float_as_uint(Vs[kk * 8 + tig + 4][n * 8 + gid]);
                    mma_tf32(o[mt][n], pa, vb);
                }
            }
            __syncwarp();
        }
    }

    #pragma unroll
    for (int mt = 0; mt < 2; mt++) {
        float inv0 = 1.f / lrow[mt][0];
        float inv1 = 1.f / lrow[mt][1];
        int r0 = qbase + mt * 16 + gid;
        float* o0 = out + (size_t)r0 * DIM + head * DHEAD;
        float* o1 = o0 + 8 * DIM;
        #pragma unroll
        for (int n = 0; n < 5; n++) {
            *(float2*)(o0 + n * 8 + 2 * tig) = make_float2(o[mt][n][0] * inv0, o[mt][n][1] * inv0);
            *(float2*)(o1 + n * 8 + 2 * tig) = make_float2(o[mt][n][2] * inv1, o[mt][n][3] * inv1);
        }
    }
}

// ---------------- cross-attention scores (f32x2) --------------------------------
__global__ __launch_bounds__(128) void cross_scores_kernel(
    const float* __restrict__ q, const float* __restrict__ kc,
    float* __restrict__ sim)
{
    __shared__ ulonglong2 Ks[M_CTX * 10];
    int head = blockIdx.y;
    int qi = blockIdx.x * 128 + threadIdx.x;
    for (int idx = threadIdx.x; idx < M_CTX * 10; idx += 128) {
        int row = idx / 10, c = idx % 10;
        Ks[idx] = *(const ulonglong2*)(kc + (size_t)row * DIM + head * DHEAD + c * 4);
    }
    __syncthreads();
    ull q2[20];
    {
        const ulonglong2* qp = (const ulonglong2*)(q + (size_t)qi * DIM + head * DHEAD);
        ull sc = dup2(SCALE);
        #pragma unroll
        for (int i = 0; i < 10; i++) {
            ulonglong2 tq = qp[i];
            q2[2 * i]     = mul2(tq.x, sc);
            q2[2 * i + 1] = mul2(tq.y, sc);
        }
    }
    float* srow = sim + ((size_t)head * N_TOK + qi) * SIM_STRIDE;
    for (int j = 0; j < M_CTX; j++) {
        ull sa = 0ull, sb = 0ull;
        const ulonglong2* kr = &Ks[j * 10];
        #pragma unroll
        for (int i = 0; i < 10; i++) {
            ulonglong2 kv = kr[i];
            fma2(sa, q2[2 * i],     kv.x);
            fma2(sb, q2[2 * i + 1], kv.y);
        }
        srow[j] = hadd2(add2(sa, sb));
    }
}

// ---------------- FCA mask + softmax (16 rows/block) ----------------------------
__global__ __launch_bounds__(128) void fca_softmax_kernel(
    float* __restrict__ sim, const float* __restrict__ fam,
    const int* __restrict__ use_fca_p)
{
    __shared__ float fam_s[M_CTX * M_CTX];
    __shared__ float srow[16][M_CTX];
    int use_fca = *use_fca_p;
    int head = blockIdx.y;
    int qbase = blockIdx.x * 16;
    for (int i = threadIdx.x; i < M_CTX * M_CTX; i += 128)
        fam_s[i] = fam[i];
    for (int idx = threadIdx.x; idx < 16 * M_CTX; idx += 128) {
        int r = idx / M_CTX, d = idx - r * M_CTX;
        srow[r][d] = sim[((size_t)head * N_TOK + qbase + r) * SIM_STRIDE + d];
    }
    __syncthreads();
    int w = threadIdx.x >> 5, lane = threadIdx.x & 31;
    int dd[3] = { lane, lane + 32, lane + 64 };

    for (int rr = 0; rr < 4; rr++) {
        int r = w * 4 + rr;
        float* grow = sim + ((size_t)head * N_TOK + qbase + r) * SIM_STRIDE;
        if (use_fca != 0) {
            float f[3];
            float fmax_local = 0.f;
            #pragma unroll
            for (int t = 0; t < 3; t++) {
                f[t] = -1.f;
                int d = dd[t];
                if (d < M_CTX) {
                    float a = 0.f;
                    for (int kk = 0; kk < M_CTX; kk++)
                        a += srow[r][kk] * fam_s[d * M_CTX + kk];
                    f[t] = fminf(fabsf(a), 1.f);
                    fmax_local = fmaxf(fmax_local, f[t]);
                }
            }
            #pragma unroll
            for (int off = 16; off; off >>= 1)
                fmax_local = fmaxf(fmax_local, __shfl_xor_sync(~0u, fmax_local, off));
            float denom = fmax_local + 1e-6f;
            __syncwarp();
            #pragma unroll
            for (int t = 0; t < 3; t++) {
                int d = dd[t];
                if (d < M_CTX) {
                    float keep = (f[t] / denom > 0.6f) ? 0.f : -50.f;
                    srow[r][d] += keep;
                }
            }
            __syncwarp();
        }
        float mloc = -1e30f;
        #pragma unroll
        for (int t = 0; t < 3; t++)
            if (dd[t] < M_CTX) mloc = fmaxf(mloc, srow[r][dd[t]]);
        #pragma unroll
        for (int off = 16; off; off >>= 1)
            mloc = fmaxf(mloc, __shfl_xor_sync(~0u, mloc, off));
        float pv[3]; float ssum = 0.f;
        #pragma unroll
        for (int t = 0; t < 3; t++) {
            pv[t] = 0.f;
            if (dd[t] < M_CTX) { pv[t] = __expf(srow[r][dd[t]] - mloc); ssum += pv[t]; }
        }
        #pragma unroll
        for (int off = 16; off; off >>= 1)
            ssum += __shfl_xor_sync(~0u, ssum, off);
        float inv = 1.f / ssum;
        #pragma unroll
        for (int t = 0; t < 3; t++)
            if (dd[t] < M_CTX) grow[dd[t]] = pv[t] * inv;
    }
}

// ---------------- cross-attention AV (f32x2) -------------------------------------
__global__ __launch_bounds__(128) void cross_av_kernel(
    const float* __restrict__ sim, const float* __restrict__ vc,
    float* __restrict__ out)
{
    __shared__ ulonglong2 Vs[M_CTX * 10];
    int head = blockIdx.y;
    int qi = blockIdx.x * 128 + threadIdx.x;
    for (int idx = threadIdx.x; idx < M_CTX * 10; idx += 128) {
        int row = idx / 10, c = idx % 10;
        Vs[idx] = *(const ulonglong2*)(vc + (size_t)row * DIM + head * DHEAD + c * 4);
    }
    __syncthreads();
    const float* srow = sim + ((size_t)head * N_TOK + qi) * SIM_STRIDE;
    ull acc[20];
    #pragma unroll
    for (int i = 0; i < 20; i++) acc[i] = 0ull;
    for (int j = 0; j < M_CTX; j++) {
        ull pd = dup2(srow[j]);
        const ulonglong2* vr = &Vs[j * 10];
        #pragma unroll
        for (int i = 0; i < 10; i++) {
            ulonglong2 vv = vr[i];
            fma2(acc[2 * i],     pd, vv.x);
            fma2(acc[2 * i + 1], pd, vv.y);
        }
    }
    ulonglong2* op = (ulonglong2*)(out + (size_t)qi * DIM + head * DHEAD);
    #pragma unroll
    for (int i = 0; i < 10; i++) {
        ulonglong2 tv;
        tv.x = acc[2 * i];
        tv.y = acc[2 * i + 1];
        op[i] = tv;
    }
}

// ---------------- GEGLU ---------------------------------------------------------
__global__ __launch_bounds__(256) void geglu_kernel(const float* __restrict__ ff,
                                                    float* __restrict__ out) {
    int idx = blockIdx.x * 256 + threadIdx.x;
    if (idx >= N_TOK * FF_INNER) return;
    int row = idx / FF_INNER, col = idx - row * FF_INNER;
    float a = ff[(size_t)row * 2 * FF_INNER + col];
    float gt = ff[(size_t)row * 2 * FF_INNER + FF_INNER + col];
    float ge = 0.5f * gt * (1.f + erff(gt * 0.70710678118654752f));
    out[idx] = a * ge;
}

// ---------------- launch ---------------------------------------------------------
extern "C" void kernel_launch(void* const* d_in, const int* in_sizes, int n_in,
                              void* d_out, int out_size)
{
    const float* x    = (const float*)d_in[0];
    const float* ctx  = (const float*)d_in[1];
    const float* fam  = (const float*)d_in[2];
    const float* g1   = (const float*)d_in[3];
    const float* b1   = (const float*)d_in[4];
    const float* g2   = (const float*)d_in[5];
    const float* b2   = (const float*)d_in[6];
    const float* g3   = (const float*)d_in[7];
    const float* b3   = (const float*)d_in[8];
    const float* Wq1  = (const float*)d_in[9];
    const float* Wk1  = (const float*)d_in[10];
    const float* Wv1  = (const float*)d_in[11];
    const float* Wo1  = (const float*)d_in[12];
    const float* bo1  = (const float*)d_in[13];
    const float* Wq2  = (const float*)d_in[14];
    const float* Wk2  = (const float*)d_in[15];
    const float* Wv2  = (const float*)d_in[16];
    const float* Wo2  = (const float*)d_in[17];
    const float* bo2  = (const float*)d_in[18];
    const float* Wff1 = (const float*)d_in[19];
    const float* bff1 = (const float*)d_in[20];
    const float* Wff2 = (const float*)d_in[21];
    const float* bff2 = (const float*)d_in[22];
    const int*   ufca = (const int*)d_in[23];
    float* out = (float*)d_out;

    float *h, *q, *k, *v, *o, *kc, *vc, *sim, *ff, *gg;
    cudaGetSymbolAddress((void**)&h,  g_h);
    cudaGetSymbolAddress((void**)&q,  g_q);
    cudaGetSymbolAddress((void**)&k,  g_k);
    cudaGetSymbolAddress((void**)&v,  g_v);
    cudaGetSymbolAddress((void**)&o,  g_o);
    cudaGetSymbolAddress((void**)&kc, g_kc);
    cudaGetSymbolAddress((void**)&vc, g_vc);
    cudaGetSymbolAddress((void**)&sim, g_sim);
    cudaGetSymbolAddress((void**)&ff, g_ff);
    cudaGetSymbolAddress((void**)&gg, g_gg);

    dim3 g_mm(DIM / 64, N_TOK / 64, 1);            // (5, 64)
    dim3 g_qkv(DIM / 64, N_TOK / 64, 3);
    dim3 g_ctx2(DIM / 64, 2, 2);                   // 77 rows -> 2 m-tiles
    dim3 g_ff1(2 * FF_INNER / 64, N_TOK / 64, 1);  // (40, 64)

    // --- block 1: self-attention ---
    ln_kernel<<<N_TOK, 128>>>(x, g1, b1, h);
    tgemm_kernel<false, false><<<g_qkv, 256>>>(h, Wq1, Wk1, Wv1, nullptr, nullptr,
                                               q, k, v, N_TOK, DIM, DIM);
    self_attn_mma_kernel<<<dim3(N_TOK / 128, HEADS), 128>>>(q, k, v, o);
    tgemm_kernel<true, true><<<g_mm, 256>>>(o, Wo1, Wo1, Wo1, bo1, x,
                                            out, out, out, N_TOK, DIM, DIM);

    // --- block 2: cross-attention with FCA ---
    ln_kernel<<<N_TOK, 128>>>(out, g2, b2, h);
    tgemm_kernel<false, false><<<g_mm, 256>>>(h, Wq2, Wq2, Wq2, nullptr, nullptr,
                                              q, q, q, N_TOK, DIM, DIM);
    tgemm_kernel<false, false><<<g_ctx2, 256>>>(ctx, Wk2, Wv2, Wv2, nullptr, nullptr,
                                                kc, vc, vc, M_CTX, DIM, CTX_DIM);
    cross_scores_kernel<<<dim3(N_TOK / 128, HEADS), 128>>>(q, kc, sim);
    fca_softmax_kernel<<<dim3(N_TOK / 16, HEADS), 128>>>(sim, fam, ufca);
    cross_av_kernel<<<dim3(N_TOK / 128, HEADS), 128>>>(sim, vc, o);
    tgemm_kernel<true, true><<<g_mm, 256>>>(o, Wo2, Wo2, Wo2, bo2, out,
                                            out, out, out, N_TOK, DIM, DIM);

    // --- block 3: GEGLU feed-forward ---
    ln_kernel<<<N_TOK, 128>>>(out, g3, b3, h);
    tgemm_kernel<true, false><<<g_ff1, 256>>>(h, Wff1, Wff1, Wff1, bff1, nullptr,
                                              ff, ff, ff, N_TOK, 2 * FF_INNER, DIM);
    geglu_kernel<<<(N_TOK * FF_INNER + 255) / 256, 256>>>(ff, gg);
    tgemm_kernel<true, true><<<g_mm, 256>>>(gg, Wff2, Wff2, Wff2, bff2, out,
                                            out, out, out, N_TOK, DIM, FF_INNER);
}